// round 12
// baseline (speedup 1.0000x reference)
#include <cuda_runtime.h>
#include <cooperative_groups.h>
#include <math.h>

namespace cg = cooperative_groups;

// ---------------- problem constants ----------------
#define BB   64      // batch
#define LS   512     // source length
#define LL   128     // law/legal length
#define TT   150     // target length
#define HH   150     // hidden
#define EE   200     // embed
#define G3   450     // 3*HH
#define VV   10000   // target vocab
#define NCH  62      // charges
#define SOS_TOK 2
#define EOS_TOK 1

#define OUT_LOSS   96000000L   // TT*BB*VV
#define OUT_CHARGE 96000001L

// ---------------- scratch (device globals; no allocation allowed) ----------------
__device__ float g_h0[BB*HH];
__device__ float g_emb_src[BB*LS*EE];
__device__ float g_gi[BB*LS*G3];
__device__ float g_enc_outs1[BB*LS*HH];
__device__ float g_chh[BB*HH];
__device__ int   g_legal_toks[BB*LL];
__device__ float g_emb_leg[BB*LL*EE];
__device__ float g_gi_leg[BB*LL*G3];
__device__ float g_legals[BB*LL*HH];
__device__ float g_att[BB*LS*LL];
__device__ float g_ca[BB*LS*HH];
__device__ float g_enc_outs[BB*LS*HH];
__device__ int   g_dec_in[BB*TT];
__device__ float g_emb_dec[BB*TT*EE];
__device__ float g_gi_dec[BB*TT*G3];
__device__ float g_dec_out[BB*TT*HH];
__device__ float g_scores[BB*TT*LS];
__device__ float g_ctx[BB*TT*HH];
__device__ float g_concat[BB*TT*2*HH];
__device__ float g_co[BB*TT*HH];
__device__ float g_nll[BB*TT];
__device__ float g_val[BB*TT];

// ---------------- small helpers ----------------
__device__ __forceinline__ float warp_max(float v){
    #pragma unroll
    for (int o=16;o;o>>=1) v = fmaxf(v, __shfl_xor_sync(0xffffffffu, v, o));
    return v;
}
__device__ __forceinline__ float warp_sum(float v){
    #pragma unroll
    for (int o=16;o;o>>=1) v += __shfl_xor_sync(0xffffffffu, v, o);
    return v;
}
template<int NW>
__device__ __forceinline__ float block_max(float v, float* red){
    v = warp_max(v);
    int w = threadIdx.x >> 5;
    if ((threadIdx.x & 31) == 0) red[w] = v;
    __syncthreads();
    float r = red[0];
    #pragma unroll
    for (int i=1;i<NW;i++) r = fmaxf(r, red[i]);
    __syncthreads();
    return r;
}
template<int NW>
__device__ __forceinline__ float block_sum(float v, float* red){
    v = warp_sum(v);
    int w = threadIdx.x >> 5;
    if ((threadIdx.x & 31) == 0) red[w] = v;
    __syncthreads();
    float r = red[0];
    #pragma unroll
    for (int i=1;i<NW;i++) r += red[i];
    __syncthreads();
    return r;
}

// ---------------- trivial kernels ----------------
__global__ void zero_kernel(float* p, long n){
    long i = (long)blockIdx.x*blockDim.x + threadIdx.x;
    if (i < n) p[i] = 0.f;
}

__global__ void gather_kernel(float* __restrict__ out, const float* __restrict__ table,
                              const int* __restrict__ toks, long nrows, int E){
    long id = (long)blockIdx.x*blockDim.x + threadIdx.x;
    if (id < nrows*(long)E){
        long r = id / E; int j = (int)(id % E);
        out[id] = table[(long)toks[r]*E + j];
    }
}

__global__ void dec_tokens_kernel(const int* __restrict__ tgts, int* __restrict__ dec_in){
    int id = blockIdx.x*blockDim.x + threadIdx.x;
    if (id < BB*TT){
        int b = id / TT, t = id % TT;
        dec_in[id] = (t == 0) ? SOS_TOK : tgts[b*TT + t - 1];
    }
}

__global__ void mean_kernel(const float* __restrict__ outs1, float* __restrict__ chh){
    int b = blockIdx.x; int j = threadIdx.x;
    if (j < HH){
        float s = 0.f;
        for (int t=0;t<LS;t++) s += outs1[((long)b*LS + t)*HH + j];
        chh[b*HH + j] = s * (1.f/LS);
    }
}

__global__ void charge_kernel(const float* __restrict__ chh, const float* __restrict__ Wc,
                              const float* __restrict__ bc, const int* __restrict__ law_tokens,
                              float* __restrict__ out_charge, int* __restrict__ legal_toks){
    int b = blockIdx.x; int tid = threadIdx.x;   // 128 threads
    __shared__ float h[HH];
    __shared__ float sc[NCH];
    __shared__ int cid;
    for (int i=tid;i<HH;i+=128) h[i] = chh[b*HH + i];
    __syncthreads();
    if (tid < NCH){
        float a = bc[tid];
        const float* w = Wc + tid*HH;
        for (int k=0;k<HH;k++) a += h[k]*w[k];
        sc[tid] = a;
        out_charge[b*NCH + tid] = a;
    }
    __syncthreads();
    if (tid == 0){
        int best = 0; float bv = sc[0];
        for (int c=1;c<NCH;c++) if (sc[c] > bv){ bv = sc[c]; best = c; }
        cid = best;
    }
    __syncthreads();
    for (int i=tid;i<LL;i+=128) legal_toks[b*LL + i] = law_tokens[cid*LL + i];
}

// ---------------- persistent GRU sequence kernel: 4-CTA cluster per batch row --------
// Grid 4*BB (64 clusters of 4 CTAs), block 128, __launch_bounds__(128,2): two CTAs from
// different clusters co-reside per SM so one cluster's sync latency hides under the
// other's matvec. Each CTA owns hidden slice [rank*38, rank*38+nj) (38,38,38,36),
// weight rows register-resident; full h replicated per CTA, double-buffered.
//
// Per-step sync: R11 used cluster.sync (~490cyc UCGABAR_WAIT). Now: aggregated
// mbarrier handshake — combine stores; __syncthreads; ONE elected thread issues one
// release-arrive per destination CTA (4 total, barrier count=4); all threads
// acquire-try_wait local barrier (TRYWAIT ~60-90cyc). This is the per-CTA-aggregated
// fix for R6's per-THREAD-arrive regression (75 serialized shared-atomics).
// Safety: stores →sb→ syncthreads →hb→ release-arrive (cumulative) →acquire-wait.
// Double-buffer race: step-t writes to buf[(t+1)&1] vs peer's step-(t-1) reads of the
// same buffer are ordered because our step-(t-1) wait required peer's step-(t-1)
// arrive, which follows peer's matvec reads.
__global__ void __cluster_dims__(4,1,1) __launch_bounds__(128,2)
gru_seq_kernel(const float* __restrict__ gi, int T,
               const float* __restrict__ Whh, const float* __restrict__ bhh,
               const float* __restrict__ hinit, long hi_stride, long hi_off,
               float* __restrict__ out)
{
    cg::cluster_group cluster = cg::this_cluster();
    int rank = cluster.block_rank();            // 0..3
    int b = blockIdx.x >> 2;                    // batch row
    int tid = threadIdx.x;

    __shared__ float h_sm[2][152];   // full h, padded for float4
    __shared__ float sg[3][40];      // this CTA's gate partials
    __shared__ __align__(8) unsigned long long mbar;

    int nj = (rank < 3) ? 38 : 36;   // 150 = 38+38+38+36
    int gate = tid / 38;             // 0..2 for tid<114
    int jj = tid - gate*38;
    bool act = (tid < 114) && (jj < nj);
    int j = rank*38 + jj;            // gate-row hidden index
    int grow = act ? (gate*HH + j) : 0;

    // register-resident weight row (padded with zeros to 152)
    float w[152];
    if (act){
        #pragma unroll
        for (int k=0;k<150;k++) w[k] = Whh[(long)grow*HH + k];
        w[150] = 0.f; w[151] = 0.f;
    } else {
        #pragma unroll
        for (int k=0;k<152;k++) w[k] = 0.f;
    }
    float bias = act ? bhh[grow] : 0.f;

    // init h buffers
    for (int k=tid;k<152;k+=128){
        h_sm[0][k] = (k < HH) ? hinit[(long)b*hi_stride + hi_off + k] : 0.f;
        h_sm[1][k] = 0.f;
    }

    // local mbarrier (expects 4 arrivals: one elected arrive from each CTA)
    uint32_t mbar_local;
    asm("{ .reg .u64 t; cvta.to.shared.u64 t, %1; cvt.u32.u64 %0, t; }"
        : "=r"(mbar_local) : "l"(&mbar));
    if (tid == 0){
        asm volatile("mbarrier.init.shared.b64 [%0], %1;" :: "r"(mbar_local), "r"(4u) : "memory");
    }
    // mapped barrier addresses for all 4 CTAs (incl. self)
    uint32_t mb0, mb1, mb2, mb3;
    asm("mapa.shared::cluster.u32 %0, %1, %2;" : "=r"(mb0) : "r"(mbar_local), "r"(0));
    asm("mapa.shared::cluster.u32 %0, %1, %2;" : "=r"(mb1) : "r"(mbar_local), "r"(1));
    asm("mapa.shared::cluster.u32 %0, %1, %2;" : "=r"(mb2) : "r"(mbar_local), "r"(2));
    asm("mapa.shared::cluster.u32 %0, %1, %2;" : "=r"(mb3) : "r"(mbar_local), "r"(3));

    // mapped h pointers for all 4 CTAs of the cluster (incl. self)
    float* ph0 = (float*)cluster.map_shared_rank((void*)&h_sm[0][0], 0);
    float* ph1 = (float*)cluster.map_shared_rank((void*)&h_sm[0][0], 1);
    float* ph2 = (float*)cluster.map_shared_rank((void*)&h_sm[0][0], 2);
    float* ph3 = (float*)cluster.map_shared_rank((void*)&h_sm[0][0], 3);

    cluster.sync();   // one-time: h init + mbarrier init visible cluster-wide

    int p = 0;
    for (int t=0;t<T;t++){
        // prefetch gi for the combine threads (overlaps the matvec)
        float gr = 0.f, gz = 0.f, gn = 0.f;
        int jc = rank*38 + tid;
        if (tid < nj){
            const float* g = gi + ((long)b*T + t)*G3;
            gr = g[jc]; gz = g[HH + jc]; gn = g[2*HH + jc];
        }

        if (tid < 114){   // padded rows compute zeros into unused sg slots
            const float4* h4 = (const float4*)&h_sm[p][0];
            float a0 = 0.f, a1 = 0.f, a2 = 0.f, a3 = 0.f;
            #pragma unroll
            for (int k4=0;k4<38;k4++){
                float4 hv = h4[k4];
                a0 += w[4*k4+0]*hv.x;
                a1 += w[4*k4+1]*hv.y;
                a2 += w[4*k4+2]*hv.z;
                a3 += w[4*k4+3]*hv.w;
            }
            sg[gate][jj] = (a0 + a1) + (a2 + a3) + bias;
        }
        __syncthreads();

        if (tid < nj){
            float r = 1.f/(1.f + expf(-(gr + sg[0][tid])));
            float z = 1.f/(1.f + expf(-(gz + sg[1][tid])));
            float n = tanhf(gn + r*sg[2][tid]);
            float hp = h_sm[p][jc];
            float hn = (1.f - z)*n + z*hp;
            int dst = (1-p)*152 + jc;
            ph0[dst] = hn;                      // broadcast to all 4 CTAs (DSMEM)
            ph1[dst] = hn;
            ph2[dst] = hn;
            ph3[dst] = hn;
            out[((long)b*T + t)*HH + jc] = hn;
        }
        __syncthreads();   // all combine stores ordered before the elected arrive

        if (tid == 0){
            // one release-arrive per destination CTA (cumulative: publishes the
            // whole CTA's stores via the syncthreads happens-before chain)
            asm volatile("mbarrier.arrive.release.cluster.shared::cluster.b64 _, [%0];" :: "r"(mb0) : "memory");
            asm volatile("mbarrier.arrive.release.cluster.shared::cluster.b64 _, [%0];" :: "r"(mb1) : "memory");
            asm volatile("mbarrier.arrive.release.cluster.shared::cluster.b64 _, [%0];" :: "r"(mb2) : "memory");
            asm volatile("mbarrier.arrive.release.cluster.shared::cluster.b64 _, [%0];" :: "r"(mb3) : "memory");
        }

        // wait for all 4 CTAs' arrivals for this step (phase parity = t&1)
        {
            uint32_t parity = (uint32_t)(t & 1);
            uint32_t done;
            asm volatile(
                "{\n\t"
                ".reg .pred P;\n\t"
                "mbarrier.try_wait.parity.acquire.cluster.shared::cta.b64 P, [%1], %2, 0x989680;\n\t"
                "selp.b32 %0, 1, 0, P;\n\t"
                "}"
                : "=r"(done) : "r"(mbar_local), "r"(parity) : "memory");
            while (!done){
                asm volatile(
                    "{\n\t"
                    ".reg .pred P;\n\t"
                    "mbarrier.try_wait.parity.acquire.cluster.shared::cta.b64 P, [%1], %2, 0x989680;\n\t"
                    "selp.b32 %0, 1, 0, P;\n\t"
                    "}"
                    : "=r"(done) : "r"(mbar_local), "r"(parity) : "memory");
            }
        }
        p ^= 1;
    }
}

// ---------------- tiled SGEMM: C = A[M,K] x (TRANSB ? B[N,K]^T : B[K,N]) ----------------
// EPI: 0=plain, 1=+bias, 2=tanh(+bias), 3=+residual, 4=+bias with [T,B,V] transposed store
template<int TRANSB, int EPI>
__global__ void gemm_kernel(const float* __restrict__ A, const float* __restrict__ Bm,
                            const float* __restrict__ bias, const float* __restrict__ res,
                            float* __restrict__ C,
                            int M, int N, int K,
                            long sA, long sB, long sC, long sR){
    int z = blockIdx.z;
    A  += (long)z*sA;
    Bm += (long)z*sB;
    C  += (long)z*sC;
    const float* R = (EPI==3) ? (res + (long)z*sR) : res;

    int m0 = blockIdx.y*64, n0 = blockIdx.x*64;
    __shared__ float As[16][68];
    __shared__ float Bs[16][68];
    int tid = threadIdx.x;
    int tx = tid & 15, ty = tid >> 4;
    float c[4][4] = {};

    for (int kk=0; kk<K; kk+=16){
        for (int idx=tid; idx<64*16; idx+=256){
            int i = idx >> 4, k = idx & 15;
            int mi = m0 + i, ki = kk + k;
            As[k][i] = (mi < M && ki < K) ? A[(long)mi*K + ki] : 0.f;
        }
        if (TRANSB){
            for (int idx=tid; idx<64*16; idx+=256){
                int j = idx >> 4, k = idx & 15;
                int nj = n0 + j, ki = kk + k;
                Bs[k][j] = (nj < N && ki < K) ? Bm[(long)nj*K + ki] : 0.f;
            }
        } else {
            for (int idx=tid; idx<64*16; idx+=256){
                int j = idx & 63, k = idx >> 6;
                int nj = n0 + j, ki = kk + k;
                Bs[k][j] = (nj < N && ki < K) ? Bm[(long)ki*N + nj] : 0.f;
            }
        }
        __syncthreads();
        #pragma unroll
        for (int k=0;k<16;k++){
            float4 a4 = *(const float4*)&As[k][ty*4];
            float4 b4 = *(const float4*)&Bs[k][tx*4];
            float af[4] = {a4.x,a4.y,a4.z,a4.w};
            float bf[4] = {b4.x,b4.y,b4.z,b4.w};
            #pragma unroll
            for (int r=0;r<4;r++)
                #pragma unroll
                for (int cc=0;cc<4;cc++)
                    c[r][cc] += af[r]*bf[cc];
        }
        __syncthreads();
    }

    #pragma unroll
    for (int r=0;r<4;r++){
        int i = m0 + ty*4 + r;
        if (i >= M) continue;
        #pragma unroll
        for (int cc=0;cc<4;cc++){
            int j = n0 + tx*4 + cc;
            if (j >= N) continue;
            float v = c[r][cc];
            if (EPI==1 || EPI==2 || EPI==4) v += bias[j];
            if (EPI==2) v = tanhf(v);
            if (EPI==3) v += R[(long)i*N + j];
            if (EPI==4){
                int bb2 = i / TT, tt2 = i % TT;
                C[((long)(tt2*BB + bb2))*N + j] = v;
            } else {
                C[(long)i*N + j] = v;
            }
        }
    }
}

// ---------------- softmaxes ----------------
__global__ void mask_softmax128(float* __restrict__ att){
    long row = blockIdx.x;
    int tid = threadIdx.x;  // 128 threads
    __shared__ float red[4];
    float x = att[row*LL + tid];
    float xm = (x == 0.f) ? -INFINITY : x;
    float M = block_max<4>(xm, red);
    float e = isinf(M) ? 0.f : expf(xm - M);
    float S = block_sum<4>(e, red);
    att[row*LL + tid] = (S > 0.f) ? e / S : 0.f;
}

__global__ void softmax512(float* __restrict__ x){
    long row = blockIdx.x;
    int tid = threadIdx.x;
    __shared__ float red[8];
    float* p = x + row*(long)LS;
    float v0 = p[tid], v1 = p[tid + 256];
    float M = block_max<8>(fmaxf(v0, v1), red);
    float e0 = expf(v0 - M), e1 = expf(v1 - M);
    float S = block_sum<8>(e0 + e1, red);
    float inv = 1.f / S;
    p[tid] = e0*inv; p[tid + 256] = e1*inv;
}

__global__ void concat_kernel(const float* __restrict__ dec_out, const float* __restrict__ ctx,
                              float* __restrict__ cat){
    long id = (long)blockIdx.x*blockDim.x + threadIdx.x;
    long n = (long)BB*TT*2*HH;
    if (id < n){
        long m = id / (2*HH); int j = (int)(id % (2*HH));
        cat[id] = (j < HH) ? dec_out[m*HH + j] : ctx[m*HH + (j - HH)];
    }
}

__global__ void nll_kernel(const float* __restrict__ logits_out, const int* __restrict__ tgts,
                           float* __restrict__ nll, float* __restrict__ validf){
    int row = blockIdx.x;           // b*TT + t
    int tid = threadIdx.x;          // 256 threads
    int b = row / TT, t = row % TT;
    const float* x = logits_out + ((long)(t*BB + b))*VV;
    __shared__ float red[8];
    float m = -INFINITY;
    for (int i=tid;i<VV;i+=256) m = fmaxf(m, x[i]);
    float M = block_max<8>(m, red);
    float s = 0.f;
    for (int i=tid;i<VV;i+=256) s += expf(x[i] - M);
    float S = block_sum<8>(s, red);
    if (tid == 0){
        int tg = tgts[row];
        float v = (tg != EOS_TOK) ? 1.f : 0.f;
        nll[row] = v * ((M + logf(S)) - x[tg]);
        validf[row] = v;
    }
}

__global__ void loss_reduce_kernel(const float* __restrict__ nll, const float* __restrict__ val,
                                   float* __restrict__ out_loss){
    __shared__ float red[8];
    int t = threadIdx.x;  // 256 threads
    float v = 0.f;
    if (t < TT){
        float s = 0.f, c = 0.f;
        for (int b=0;b<BB;b++){ s += nll[b*TT + t]; c += val[b*TT + t]; }
        v = s / fmaxf(c, 1.f);
    }
    float tot = block_sum<8>(v, red);
    if (t == 0) out_loss[0] = tot;
}

// ---------------- host side ----------------
static void launch_gemm(int transb, int epi,
                        const float* A, const float* Bm, const float* bias, const float* res,
                        float* C, int M, int N, int K,
                        long sA, long sB, long sC, long sR, int batch){
    dim3 gr((N + 63)/64, (M + 63)/64, batch);
    dim3 bl(256);
    if (transb){
        if (epi == 0)      gemm_kernel<1,0><<<gr,bl>>>(A,Bm,bias,res,C,M,N,K,sA,sB,sC,sR);
        else if (epi == 1) gemm_kernel<1,1><<<gr,bl>>>(A,Bm,bias,res,C,M,N,K,sA,sB,sC,sR);
        else if (epi == 2) gemm_kernel<1,2><<<gr,bl>>>(A,Bm,bias,res,C,M,N,K,sA,sB,sC,sR);
        else               gemm_kernel<1,4><<<gr,bl>>>(A,Bm,bias,res,C,M,N,K,sA,sB,sC,sR);
    } else {
        if (epi == 0)      gemm_kernel<0,0><<<gr,bl>>>(A,Bm,bias,res,C,M,N,K,sA,sB,sC,sR);
        else               gemm_kernel<0,3><<<gr,bl>>>(A,Bm,bias,res,C,M,N,K,sA,sB,sC,sR);
    }
}

template<typename T> static T* sym(const void* s){
    void* p = nullptr;
    cudaGetSymbolAddress(&p, s);
    return (T*)p;
}

extern "C" void kernel_launch(void* const* d_in, const int* in_sizes, int n_in,
                              void* d_out, int out_size){
    const int*   srcs        = (const int*)  d_in[0];
    const int*   tgts        = (const int*)  d_in[1];
    const int*   law_tokens  = (const int*)  d_in[2];
    const float* src_embed   = (const float*)d_in[3];
    const float* enc_rnn_Wih = (const float*)d_in[4];
    const float* enc_rnn_Whh = (const float*)d_in[5];
    const float* enc_rnn_bih = (const float*)d_in[6];
    const float* enc_rnn_bhh = (const float*)d_in[7];
    const float* enc_gru_Wih = (const float*)d_in[8];
    const float* enc_gru_Whh = (const float*)d_in[9];
    const float* enc_gru_bih = (const float*)d_in[10];
    const float* enc_gru_bhh = (const float*)d_in[11];
    const float* dec_embed   = (const float*)d_in[12];
    const float* dec_rnn_Wih = (const float*)d_in[13];
    const float* dec_rnn_Whh = (const float*)d_in[14];
    const float* dec_rnn_bih = (const float*)d_in[15];
    const float* dec_rnn_bhh = (const float*)d_in[16];
    const float* Ww          = (const float*)d_in[17];
    const float* bw          = (const float*)d_in[18];
    const float* Wp          = (const float*)d_in[19];
    const float* bp          = (const float*)d_in[20];
    const float* Wc          = (const float*)d_in[21];
    const float* bc          = (const float*)d_in[22];
    float* out = (float*)d_out;

    float* h0       = sym<float>(g_h0);
    float* emb_src  = sym<float>(g_emb_src);
    float* gi       = sym<float>(g_gi);
    float* enc1     = sym<float>(g_enc_outs1);
    float* chh      = sym<float>(g_chh);
    int*   leg_toks = sym<int>(g_legal_toks);
    float* emb_leg  = sym<float>(g_emb_leg);
    float* gi_leg   = sym<float>(g_gi_leg);
    float* legals   = sym<float>(g_legals);
    float* att      = sym<float>(g_att);
    float* ca       = sym<float>(g_ca);
    float* enc2     = sym<float>(g_enc_outs);
    int*   dec_in   = sym<int>(g_dec_in);
    float* emb_dec  = sym<float>(g_emb_dec);
    float* gi_dec   = sym<float>(g_gi_dec);
    float* dec_outb = sym<float>(g_dec_out);
    float* scores   = sym<float>(g_scores);
    float* ctx      = sym<float>(g_ctx);
    float* cat      = sym<float>(g_concat);
    float* co       = sym<float>(g_co);
    float* nll      = sym<float>(g_nll);
    float* valf     = sym<float>(g_val);

    // h0 = zeros
    zero_kernel<<<(BB*HH + 255)/256, 256>>>(h0, BB*HH);

    // ---- encoder pass 1 ----
    {
        long n = (long)BB*LS*EE;
        gather_kernel<<<(unsigned)((n + 255)/256), 256>>>(emb_src, src_embed, srcs, (long)BB*LS, EE);
    }
    launch_gemm(1, 1, emb_src, enc_rnn_Wih, enc_rnn_bih, nullptr, gi,
                BB*LS, G3, EE, 0, 0, 0, 0, 1);
    gru_seq_kernel<<<4*BB, 128>>>(gi, LS, enc_rnn_Whh, enc_rnn_bhh, h0, HH, 0, enc1);

    // ---- charge prediction + legal tokens ----
    mean_kernel<<<BB, 160>>>(enc1, chh);
    charge_kernel<<<BB, 128>>>(chh, Wc, bc, law_tokens, out + OUT_CHARGE, leg_toks);

    // ---- legal encoding (same encoder rnn) ----
    {
        long n = (long)BB*LL*EE;
        gather_kernel<<<(unsigned)((n + 255)/256), 256>>>(emb_leg, src_embed, leg_toks, (long)BB*LL, EE);
    }
    launch_gemm(1, 1, emb_leg, enc_rnn_Wih, enc_rnn_bih, nullptr, gi_leg,
                BB*LL, G3, EE, 0, 0, 0, 0, 1);
    gru_seq_kernel<<<4*BB, 128>>>(gi_leg, LL, enc_rnn_Whh, enc_rnn_bhh, h0, HH, 0, legals);

    // ---- mask attention: att = enc1 @ legals^T, masked softmax, ca = aw@legals + enc1 ----
    launch_gemm(1, 0, enc1, legals, nullptr, nullptr, att,
                LS, LL, HH, (long)LS*HH, (long)LL*HH, (long)LS*LL, 0, BB);
    mask_softmax128<<<BB*LS, 128>>>(att);
    launch_gemm(0, 3, att, legals, nullptr, enc1, ca,
                LS, HH, LL, (long)LS*LL, (long)LL*HH, (long)LS*HH, (long)LS*HH, BB);

    // ---- encoder pass 2 ----
    launch_gemm(1, 1, ca, enc_gru_Wih, enc_gru_bih, nullptr, gi,
                BB*LS, G3, HH, 0, 0, 0, 0, 1);
    gru_seq_kernel<<<4*BB, 128>>>(gi, LS, enc_gru_Whh, enc_gru_bhh, h0, HH, 0, enc2);

    // ---- decoder GRU (teacher forcing), h0 = enc2[:,511,:] ----
    dec_tokens_kernel<<<(BB*TT + 255)/256, 256>>>(tgts, dec_in);
    {
        long n = (long)BB*TT*EE;
        gather_kernel<<<(unsigned)((n + 255)/256), 256>>>(emb_dec, dec_embed, dec_in, (long)BB*TT, EE);
    }
    launch_gemm(1, 1, emb_dec, dec_rnn_Wih, dec_rnn_bih, nullptr, gi_dec,
                BB*TT, G3, EE, 0, 0, 0, 0, 1);
    gru_seq_kernel<<<4*BB, 128>>>(gi_dec, TT, dec_rnn_Whh, dec_rnn_bhh,
                                  enc2, (long)LS*HH, (long)(LS-1)*HH, dec_outb);

    // ---- decoder attention ----
    launch_gemm(1, 0, dec_outb, enc2, nullptr, nullptr, scores,
                TT, LS, HH, (long)TT*HH, (long)LS*HH, (long)TT*LS, 0, BB);
    softmax512<<<BB*TT, 256>>>(scores);
    launch_gemm(0, 0, scores, enc2, nullptr, nullptr, ctx,
                TT, HH, LS, (long)TT*LS, (long)LS*HH, (long)TT*HH, 0, BB);

    // ---- co = tanh([dec_out|ctx] @ Ww^T + bw) ----
    {
        long n = (long)BB*TT*2*HH;
        concat_kernel<<<(unsigned)((n + 255)/256), 256>>>(dec_outb, ctx, cat);
    }
    launch_gemm(1, 2, cat, Ww, bw, nullptr, co,
                BB*TT, HH, 2*HH, 0, 0, 0, 0, 1);

    // ---- logits = co @ Wp^T + bp, stored transposed [T,B,1,V] directly into d_out ----
    launch_gemm(1, 4, co, Wp, bp, nullptr, out,
                BB*TT, VV, HH, 0, 0, 0, 0, 1);

    // ---- loss ----
    nll_kernel<<<BB*TT, 256>>>(out, tgts, nll, valf);
    loss_reduce_kernel<<<1, 256>>>(nll, valf, out + OUT_LOSS);
}

// round 13
// speedup vs baseline: 1.5652x; 1.5652x over previous
#include <cuda_runtime.h>
#include <cooperative_groups.h>
#include <math.h>

namespace cg = cooperative_groups;

// ---------------- problem constants ----------------
#define BB   64      // batch
#define LS   512     // source length
#define LL   128     // law/legal length
#define TT   150     // target length
#define HH   150     // hidden
#define EE   200     // embed
#define G3   450     // 3*HH
#define VV   10000   // target vocab
#define NCH  62      // charges
#define SOS_TOK 2
#define EOS_TOK 1

#define OUT_LOSS   96000000L   // TT*BB*VV
#define OUT_CHARGE 96000001L

// ---------------- scratch (device globals; no allocation allowed) ----------------
__device__ float g_h0[BB*HH];
__device__ float g_emb_src[BB*LS*EE];
__device__ float g_gi[BB*LS*G3];
__device__ float g_enc_outs1[BB*LS*HH];
__device__ float g_chh[BB*HH];
__device__ int   g_legal_toks[BB*LL];
__device__ float g_emb_leg[BB*LL*EE];
__device__ float g_gi_leg[BB*LL*G3];
__device__ float g_legals[BB*LL*HH];
__device__ float g_att[BB*LS*LL];
__device__ float g_ca[BB*LS*HH];
__device__ float g_enc_outs[BB*LS*HH];
__device__ int   g_dec_in[BB*TT];
__device__ float g_emb_dec[BB*TT*EE];
__device__ float g_gi_dec[BB*TT*G3];
__device__ float g_dec_out[BB*TT*HH];
__device__ float g_scores[BB*TT*LS];
__device__ float g_ctx[BB*TT*HH];
__device__ float g_concat[BB*TT*2*HH];
__device__ float g_co[BB*TT*HH];
__device__ float g_nll[BB*TT];
__device__ float g_val[BB*TT];

// ---------------- small helpers ----------------
__device__ __forceinline__ float warp_max(float v){
    #pragma unroll
    for (int o=16;o;o>>=1) v = fmaxf(v, __shfl_xor_sync(0xffffffffu, v, o));
    return v;
}
__device__ __forceinline__ float warp_sum(float v){
    #pragma unroll
    for (int o=16;o;o>>=1) v += __shfl_xor_sync(0xffffffffu, v, o);
    return v;
}
template<int NW>
__device__ __forceinline__ float block_max(float v, float* red){
    v = warp_max(v);
    int w = threadIdx.x >> 5;
    if ((threadIdx.x & 31) == 0) red[w] = v;
    __syncthreads();
    float r = red[0];
    #pragma unroll
    for (int i=1;i<NW;i++) r = fmaxf(r, red[i]);
    __syncthreads();
    return r;
}
template<int NW>
__device__ __forceinline__ float block_sum(float v, float* red){
    v = warp_sum(v);
    int w = threadIdx.x >> 5;
    if ((threadIdx.x & 31) == 0) red[w] = v;
    __syncthreads();
    float r = red[0];
    #pragma unroll
    for (int i=1;i<NW;i++) r += red[i];
    __syncthreads();
    return r;
}

__device__ __forceinline__ uint32_t f2tf32(float f){
    uint32_t u;
    asm("cvt.rna.tf32.f32 %0, %1;" : "=r"(u) : "f"(f));
    return u;
}

// ---------------- trivial kernels ----------------
__global__ void zero_kernel(float* p, long n){
    long i = (long)blockIdx.x*blockDim.x + threadIdx.x;
    if (i < n) p[i] = 0.f;
}

__global__ void gather_kernel(float* __restrict__ out, const float* __restrict__ table,
                              const int* __restrict__ toks, long nrows, int E){
    long id = (long)blockIdx.x*blockDim.x + threadIdx.x;
    if (id < nrows*(long)E){
        long r = id / E; int j = (int)(id % E);
        out[id] = table[(long)toks[r]*E + j];
    }
}

__global__ void dec_tokens_kernel(const int* __restrict__ tgts, int* __restrict__ dec_in){
    int id = blockIdx.x*blockDim.x + threadIdx.x;
    if (id < BB*TT){
        int b = id / TT, t = id % TT;
        dec_in[id] = (t == 0) ? SOS_TOK : tgts[b*TT + t - 1];
    }
}

__global__ void mean_kernel(const float* __restrict__ outs1, float* __restrict__ chh){
    int b = blockIdx.x; int j = threadIdx.x;
    if (j < HH){
        float s = 0.f;
        for (int t=0;t<LS;t++) s += outs1[((long)b*LS + t)*HH + j];
        chh[b*HH + j] = s * (1.f/LS);
    }
}

__global__ void charge_kernel(const float* __restrict__ chh, const float* __restrict__ Wc,
                              const float* __restrict__ bc, const int* __restrict__ law_tokens,
                              float* __restrict__ out_charge, int* __restrict__ legal_toks){
    int b = blockIdx.x; int tid = threadIdx.x;   // 128 threads
    __shared__ float h[HH];
    __shared__ float sc[NCH];
    __shared__ int cid;
    for (int i=tid;i<HH;i+=128) h[i] = chh[b*HH + i];
    __syncthreads();
    if (tid < NCH){
        float a = bc[tid];
        const float* w = Wc + tid*HH;
        for (int k=0;k<HH;k++) a += h[k]*w[k];
        sc[tid] = a;
        out_charge[b*NCH + tid] = a;
    }
    __syncthreads();
    if (tid == 0){
        int best = 0; float bv = sc[0];
        for (int c=1;c<NCH;c++) if (sc[c] > bv){ bv = sc[c]; best = c; }
        cid = best;
    }
    __syncthreads();
    for (int i=tid;i<LL;i+=128) legal_toks[b*LL + i] = law_tokens[cid*LL + i];
}

// ---------------- persistent GRU sequence kernel: 4-CTA cluster per batch row --------
// (R11 configuration — best measured. cluster.sync per step; both mbarrier-handshake
//  variants (R6 per-thread, R12 aggregated) regressed. Do not touch.)
__global__ void __cluster_dims__(4,1,1) __launch_bounds__(128,2)
gru_seq_kernel(const float* __restrict__ gi, int T,
               const float* __restrict__ Whh, const float* __restrict__ bhh,
               const float* __restrict__ hinit, long hi_stride, long hi_off,
               float* __restrict__ out)
{
    cg::cluster_group cluster = cg::this_cluster();
    int rank = cluster.block_rank();            // 0..3
    int b = blockIdx.x >> 2;                    // batch row
    int tid = threadIdx.x;

    __shared__ float h_sm[2][152];   // full h, padded for float4
    __shared__ float sg[3][40];      // this CTA's gate partials

    int nj = (rank < 3) ? 38 : 36;   // 150 = 38+38+38+36
    int gate = tid / 38;             // 0..2 for tid<114
    int jj = tid - gate*38;
    bool act = (tid < 114) && (jj < nj);
    int j = rank*38 + jj;            // gate-row hidden index
    int grow = act ? (gate*HH + j) : 0;

    // register-resident weight row (padded with zeros to 152)
    float w[152];
    if (act){
        #pragma unroll
        for (int k=0;k<150;k++) w[k] = Whh[(long)grow*HH + k];
        w[150] = 0.f; w[151] = 0.f;
    } else {
        #pragma unroll
        for (int k=0;k<152;k++) w[k] = 0.f;
    }
    float bias = act ? bhh[grow] : 0.f;

    // init h buffers
    for (int k=tid;k<152;k+=128){
        h_sm[0][k] = (k < HH) ? hinit[(long)b*hi_stride + hi_off + k] : 0.f;
        h_sm[1][k] = 0.f;
    }

    // mapped h pointers for all 4 CTAs of the cluster (incl. self)
    float* ph0 = (float*)cluster.map_shared_rank((void*)&h_sm[0][0], 0);
    float* ph1 = (float*)cluster.map_shared_rank((void*)&h_sm[0][0], 1);
    float* ph2 = (float*)cluster.map_shared_rank((void*)&h_sm[0][0], 2);
    float* ph3 = (float*)cluster.map_shared_rank((void*)&h_sm[0][0], 3);

    cluster.sync();   // init visible before any peer writes

    int p = 0;
    for (int t=0;t<T;t++){
        // prefetch gi for the combine threads (overlaps the matvec)
        float gr = 0.f, gz = 0.f, gn = 0.f;
        int jc = rank*38 + tid;
        if (tid < nj){
            const float* g = gi + ((long)b*T + t)*G3;
            gr = g[jc]; gz = g[HH + jc]; gn = g[2*HH + jc];
        }

        if (tid < 114){   // padded rows compute zeros into unused sg slots
            const float4* h4 = (const float4*)&h_sm[p][0];
            float a0 = 0.f, a1 = 0.f, a2 = 0.f, a3 = 0.f;
            #pragma unroll
            for (int k4=0;k4<38;k4++){
                float4 hv = h4[k4];
                a0 += w[4*k4+0]*hv.x;
                a1 += w[4*k4+1]*hv.y;
                a2 += w[4*k4+2]*hv.z;
                a3 += w[4*k4+3]*hv.w;
            }
            sg[gate][jj] = (a0 + a1) + (a2 + a3) + bias;
        }
        __syncthreads();

        if (tid < nj){
            float r = 1.f/(1.f + expf(-(gr + sg[0][tid])));
            float z = 1.f/(1.f + expf(-(gz + sg[1][tid])));
            float n = tanhf(gn + r*sg[2][tid]);
            float hp = h_sm[p][jc];
            float hn = (1.f - z)*n + z*hp;
            int dst = (1-p)*152 + jc;
            ph0[dst] = hn;                      // broadcast to all 4 CTAs (DSMEM)
            ph1[dst] = hn;
            ph2[dst] = hn;
            ph3[dst] = hn;
            out[((long)b*T + t)*HH + jc] = hn;
        }
        cluster.sync();   // all CTAs' h slices visible everywhere; orders sg reuse
        p ^= 1;
    }
}

// ---------------- tiled SGEMM: C = A[M,K] x (TRANSB ? B[N,K]^T : B[K,N]) ----------------
// EPI: 0=plain, 1=+bias, 2=tanh(+bias), 3=+residual
template<int TRANSB, int EPI>
__global__ void gemm_kernel(const float* __restrict__ A, const float* __restrict__ Bm,
                            const float* __restrict__ bias, const float* __restrict__ res,
                            float* __restrict__ C,
                            int M, int N, int K,
                            long sA, long sB, long sC, long sR){
    int z = blockIdx.z;
    A  += (long)z*sA;
    Bm += (long)z*sB;
    C  += (long)z*sC;
    const float* R = (EPI==3) ? (res + (long)z*sR) : res;

    int m0 = blockIdx.y*64, n0 = blockIdx.x*64;
    __shared__ float As[16][68];
    __shared__ float Bs[16][68];
    int tid = threadIdx.x;
    int tx = tid & 15, ty = tid >> 4;
    float c[4][4] = {};

    for (int kk=0; kk<K; kk+=16){
        for (int idx=tid; idx<64*16; idx+=256){
            int i = idx >> 4, k = idx & 15;
            int mi = m0 + i, ki = kk + k;
            As[k][i] = (mi < M && ki < K) ? A[(long)mi*K + ki] : 0.f;
        }
        if (TRANSB){
            for (int idx=tid; idx<64*16; idx+=256){
                int j = idx >> 4, k = idx & 15;
                int nj = n0 + j, ki = kk + k;
                Bs[k][j] = (nj < N && ki < K) ? Bm[(long)nj*K + ki] : 0.f;
            }
        } else {
            for (int idx=tid; idx<64*16; idx+=256){
                int j = idx & 63, k = idx >> 6;
                int nj = n0 + j, ki = kk + k;
                Bs[k][j] = (nj < N && ki < K) ? Bm[(long)ki*N + nj] : 0.f;
            }
        }
        __syncthreads();
        #pragma unroll
        for (int k=0;k<16;k++){
            float4 a4 = *(const float4*)&As[k][ty*4];
            float4 b4 = *(const float4*)&Bs[k][tx*4];
            float af[4] = {a4.x,a4.y,a4.z,a4.w};
            float bf[4] = {b4.x,b4.y,b4.z,b4.w};
            #pragma unroll
            for (int r=0;r<4;r++)
                #pragma unroll
                for (int cc=0;cc<4;cc++)
                    c[r][cc] += af[r]*bf[cc];
        }
        __syncthreads();
    }

    #pragma unroll
    for (int r=0;r<4;r++){
        int i = m0 + ty*4 + r;
        if (i >= M) continue;
        #pragma unroll
        for (int cc=0;cc<4;cc++){
            int j = n0 + tx*4 + cc;
            if (j >= N) continue;
            float v = c[r][cc];
            if (EPI==1 || EPI==2) v += bias[j];
            if (EPI==2) v = tanhf(v);
            if (EPI==3) v += R[(long)i*N + j];
            C[(long)i*N + j] = v;
        }
    }
}

// ---------------- tf32 tensor-core GEMM for logits: C = A[M,K] @ B[N,K]^T + bias -----
// Stored transposed: C[(tt*BB+bb)*N + j] for row i = bb*TT+tt  ([T,B,1,V] output layout).
// 128x128 block tile, 256 threads = 8 warps in 2(M)x4(N), warp tile 64x32,
// mma.sync.aligned.m16n8k8 tf32 with fp32 accumulate. smem stride 136 words makes
// fragment LDS bank-conflict-free (rows offset by 8 banks for t4=0..3, +g spans 8).
#define TFST 136
__global__ void __launch_bounds__(256)
logits_tf32_kernel(const float* __restrict__ A, const float* __restrict__ Bm,
                   const float* __restrict__ bias, float* __restrict__ C,
                   int M, int N, int K){
    __shared__ float As[16*TFST];
    __shared__ float Bs[16*TFST];
    int m0 = blockIdx.y*128, n0 = blockIdx.x*128;
    int tid = threadIdx.x;
    int lane = tid & 31, warp = tid >> 5;
    int wm = warp >> 2, wn = warp & 3;      // 2 x 4 warp grid
    int g = lane >> 2, t4 = lane & 3;       // groupID / threadID-in-group

    float c[4][4][4];
    #pragma unroll
    for (int a=0;a<4;a++)
        #pragma unroll
        for (int bq=0;bq<4;bq++)
            #pragma unroll
            for (int r=0;r<4;r++) c[a][bq][r] = 0.f;

    for (int kk=0; kk<K; kk+=16){
        #pragma unroll
        for (int l=0;l<8;l++){
            int idx = tid + l*256;
            int i = idx >> 4, k = idx & 15;
            int ki = kk + k;
            As[k*TFST + i] = (ki < K) ? A[(long)(m0+i)*K + ki] : 0.f;  // M % 128 == 0
            int nj = n0 + i;
            Bs[k*TFST + i] = (nj < N && ki < K) ? Bm[(long)nj*K + ki] : 0.f;
        }
        __syncthreads();
        #pragma unroll
        for (int k8=0;k8<16;k8+=8){
            uint32_t bf[4][2];
            #pragma unroll
            for (int nt=0;nt<4;nt++){
                int nb = wn*32 + nt*8 + g;
                bf[nt][0] = f2tf32(Bs[(k8+t4)*TFST + nb]);
                bf[nt][1] = f2tf32(Bs[(k8+t4+4)*TFST + nb]);
            }
            #pragma unroll
            for (int mt=0;mt<4;mt++){
                int mb = wm*64 + mt*16 + g;
                uint32_t a0 = f2tf32(As[(k8+t4)*TFST + mb]);
                uint32_t a1 = f2tf32(As[(k8+t4)*TFST + mb + 8]);
                uint32_t a2 = f2tf32(As[(k8+t4+4)*TFST + mb]);
                uint32_t a3 = f2tf32(As[(k8+t4+4)*TFST + mb + 8]);
                #pragma unroll
                for (int nt=0;nt<4;nt++){
                    asm volatile(
                        "mma.sync.aligned.m16n8k8.row.col.f32.tf32.tf32.f32 "
                        "{%0,%1,%2,%3}, {%4,%5,%6,%7}, {%8,%9}, {%0,%1,%2,%3};"
                        : "+f"(c[mt][nt][0]), "+f"(c[mt][nt][1]),
                          "+f"(c[mt][nt][2]), "+f"(c[mt][nt][3])
                        : "r"(a0), "r"(a1), "r"(a2), "r"(a3),
                          "r"(bf[nt][0]), "r"(bf[nt][1]));
                }
            }
        }
        __syncthreads();
    }

    // epilogue: bias + transposed [T,B,V] store
    // c frag mapping: c0:(g, 2t4) c1:(g, 2t4+1) c2:(g+8, 2t4) c3:(g+8, 2t4+1)
    #pragma unroll
    for (int mt=0;mt<4;mt++){
        int i0 = m0 + wm*64 + mt*16 + g;
        #pragma unroll
        for (int nt=0;nt<4;nt++){
            int j0 = n0 + wn*32 + nt*8 + t4*2;
            #pragma unroll
            for (int rr=0;rr<2;rr++){
                int i = i0 + rr*8;
                int bb2 = i / TT, tt2 = i % TT;
                long rowoff = ((long)(tt2*BB + bb2))*N;
                #pragma unroll
                for (int cc2=0;cc2<2;cc2++){
                    int j = j0 + cc2;
                    if (j < N)
                        C[rowoff + j] = c[mt][nt][rr*2 + cc2] + bias[j];
                }
            }
        }
    }
}

// ---------------- softmaxes ----------------
__global__ void mask_softmax128(float* __restrict__ att){
    long row = blockIdx.x;
    int tid = threadIdx.x;  // 128 threads
    __shared__ float red[4];
    float x = att[row*LL + tid];
    float xm = (x == 0.f) ? -INFINITY : x;
    float M = block_max<4>(xm, red);
    float e = isinf(M) ? 0.f : expf(xm - M);
    float S = block_sum<4>(e, red);
    att[row*LL + tid] = (S > 0.f) ? e / S : 0.f;
}

__global__ void softmax512(float* __restrict__ x){
    long row = blockIdx.x;
    int tid = threadIdx.x;
    __shared__ float red[8];
    float* p = x + row*(long)LS;
    float v0 = p[tid], v1 = p[tid + 256];
    float M = block_max<8>(fmaxf(v0, v1), red);
    float e0 = expf(v0 - M), e1 = expf(v1 - M);
    float S = block_sum<8>(e0 + e1, red);
    float inv = 1.f / S;
    p[tid] = e0*inv; p[tid + 256] = e1*inv;
}

__global__ void concat_kernel(const float* __restrict__ dec_out, const float* __restrict__ ctx,
                              float* __restrict__ cat){
    long id = (long)blockIdx.x*blockDim.x + threadIdx.x;
    long n = (long)BB*TT*2*HH;
    if (id < n){
        long m = id / (2*HH); int j = (int)(id % (2*HH));
        cat[id] = (j < HH) ? dec_out[m*HH + j] : ctx[m*HH + (j - HH)];
    }
}

__global__ void nll_kernel(const float* __restrict__ logits_out, const int* __restrict__ tgts,
                           float* __restrict__ nll, float* __restrict__ validf){
    int row = blockIdx.x;           // b*TT + t
    int tid = threadIdx.x;          // 256 threads
    int b = row / TT, t = row % TT;
    const float* x = logits_out + ((long)(t*BB + b))*VV;
    __shared__ float red[8];
    float m = -INFINITY;
    for (int i=tid;i<VV;i+=256) m = fmaxf(m, x[i]);
    float M = block_max<8>(m, red);
    float s = 0.f;
    for (int i=tid;i<VV;i+=256) s += expf(x[i] - M);
    float S = block_sum<8>(s, red);
    if (tid == 0){
        int tg = tgts[row];
        float v = (tg != EOS_TOK) ? 1.f : 0.f;
        nll[row] = v * ((M + logf(S)) - x[tg]);
        validf[row] = v;
    }
}

__global__ void loss_reduce_kernel(const float* __restrict__ nll, const float* __restrict__ val,
                                   float* __restrict__ out_loss){
    __shared__ float red[8];
    int t = threadIdx.x;  // 256 threads
    float v = 0.f;
    if (t < TT){
        float s = 0.f, c = 0.f;
        for (int b=0;b<BB;b++){ s += nll[b*TT + t]; c += val[b*TT + t]; }
        v = s / fmaxf(c, 1.f);
    }
    float tot = block_sum<8>(v, red);
    if (t == 0) out_loss[0] = tot;
}

// ---------------- host side ----------------
static void launch_gemm(int transb, int epi,
                        const float* A, const float* Bm, const float* bias, const float* res,
                        float* C, int M, int N, int K,
                        long sA, long sB, long sC, long sR, int batch){
    dim3 gr((N + 63)/64, (M + 63)/64, batch);
    dim3 bl(256);
    if (transb){
        if (epi == 0)      gemm_kernel<1,0><<<gr,bl>>>(A,Bm,bias,res,C,M,N,K,sA,sB,sC,sR);
        else if (epi == 1) gemm_kernel<1,1><<<gr,bl>>>(A,Bm,bias,res,C,M,N,K,sA,sB,sC,sR);
        else               gemm_kernel<1,2><<<gr,bl>>>(A,Bm,bias,res,C,M,N,K,sA,sB,sC,sR);
    } else {
        if (epi == 0)      gemm_kernel<0,0><<<gr,bl>>>(A,Bm,bias,res,C,M,N,K,sA,sB,sC,sR);
        else               gemm_kernel<0,3><<<gr,bl>>>(A,Bm,bias,res,C,M,N,K,sA,sB,sC,sR);
    }
}

template<typename T> static T* sym(const void* s){
    void* p = nullptr;
    cudaGetSymbolAddress(&p, s);
    return (T*)p;
}

extern "C" void kernel_launch(void* const* d_in, const int* in_sizes, int n_in,
                              void* d_out, int out_size){
    const int*   srcs        = (const int*)  d_in[0];
    const int*   tgts        = (const int*)  d_in[1];
    const int*   law_tokens  = (const int*)  d_in[2];
    const float* src_embed   = (const float*)d_in[3];
    const float* enc_rnn_Wih = (const float*)d_in[4];
    const float* enc_rnn_Whh = (const float*)d_in[5];
    const float* enc_rnn_bih = (const float*)d_in[6];
    const float* enc_rnn_bhh = (const float*)d_in[7];
    const float* enc_gru_Wih = (const float*)d_in[8];
    const float* enc_gru_Whh = (const float*)d_in[9];
    const float* enc_gru_bih = (const float*)d_in[10];
    const float* enc_gru_bhh = (const float*)d_in[11];
    const float* dec_embed   = (const float*)d_in[12];
    const float* dec_rnn_Wih = (const float*)d_in[13];
    const float* dec_rnn_Whh = (const float*)d_in[14];
    const float* dec_rnn_bih = (const float*)d_in[15];
    const float* dec_rnn_bhh = (const float*)d_in[16];
    const float* Ww          = (const float*)d_in[17];
    const float* bw          = (const float*)d_in[18];
    const float* Wp          = (const float*)d_in[19];
    const float* bp          = (const float*)d_in[20];
    const float* Wc          = (const float*)d_in[21];
    const float* bc          = (const float*)d_in[22];
    float* out = (float*)d_out;

    float* h0       = sym<float>(g_h0);
    float* emb_src  = sym<float>(g_emb_src);
    float* gi       = sym<float>(g_gi);
    float* enc1     = sym<float>(g_enc_outs1);
    float* chh      = sym<float>(g_chh);
    int*   leg_toks = sym<int>(g_legal_toks);
    float* emb_leg  = sym<float>(g_emb_leg);
    float* gi_leg   = sym<float>(g_gi_leg);
    float* legals   = sym<float>(g_legals);
    float* att      = sym<float>(g_att);
    float* ca       = sym<float>(g_ca);
    float* enc2     = sym<float>(g_enc_outs);
    int*   dec_in   = sym<int>(g_dec_in);
    float* emb_dec  = sym<float>(g_emb_dec);
    float* gi_dec   = sym<float>(g_gi_dec);
    float* dec_outb = sym<float>(g_dec_out);
    float* scores   = sym<float>(g_scores);
    float* ctx      = sym<float>(g_ctx);
    float* cat      = sym<float>(g_concat);
    float* co       = sym<float>(g_co);
    float* nll      = sym<float>(g_nll);
    float* valf     = sym<float>(g_val);

    // h0 = zeros
    zero_kernel<<<(BB*HH + 255)/256, 256>>>(h0, BB*HH);

    // ---- encoder pass 1 ----
    {
        long n = (long)BB*LS*EE;
        gather_kernel<<<(unsigned)((n + 255)/256), 256>>>(emb_src, src_embed, srcs, (long)BB*LS, EE);
    }
    launch_gemm(1, 1, emb_src, enc_rnn_Wih, enc_rnn_bih, nullptr, gi,
                BB*LS, G3, EE, 0, 0, 0, 0, 1);
    gru_seq_kernel<<<4*BB, 128>>>(gi, LS, enc_rnn_Whh, enc_rnn_bhh, h0, HH, 0, enc1);

    // ---- charge prediction + legal tokens ----
    mean_kernel<<<BB, 160>>>(enc1, chh);
    charge_kernel<<<BB, 128>>>(chh, Wc, bc, law_tokens, out + OUT_CHARGE, leg_toks);

    // ---- legal encoding (same encoder rnn) ----
    {
        long n = (long)BB*LL*EE;
        gather_kernel<<<(unsigned)((n + 255)/256), 256>>>(emb_leg, src_embed, leg_toks, (long)BB*LL, EE);
    }
    launch_gemm(1, 1, emb_leg, enc_rnn_Wih, enc_rnn_bih, nullptr, gi_leg,
                BB*LL, G3, EE, 0, 0, 0, 0, 1);
    gru_seq_kernel<<<4*BB, 128>>>(gi_leg, LL, enc_rnn_Whh, enc_rnn_bhh, h0, HH, 0, legals);

    // ---- mask attention: att = enc1 @ legals^T, masked softmax, ca = aw@legals + enc1 ----
    launch_gemm(1, 0, enc1, legals, nullptr, nullptr, att,
                LS, LL, HH, (long)LS*HH, (long)LL*HH, (long)LS*LL, 0, BB);
    mask_softmax128<<<BB*LS, 128>>>(att);
    launch_gemm(0, 3, att, legals, nullptr, enc1, ca,
                LS, HH, LL, (long)LS*LL, (long)LL*HH, (long)LS*HH, (long)LS*HH, BB);

    // ---- encoder pass 2 ----
    launch_gemm(1, 1, ca, enc_gru_Wih, enc_gru_bih, nullptr, gi,
                BB*LS, G3, HH, 0, 0, 0, 0, 1);
    gru_seq_kernel<<<4*BB, 128>>>(gi, LS, enc_gru_Whh, enc_gru_bhh, h0, HH, 0, enc2);

    // ---- decoder GRU (teacher forcing), h0 = enc2[:,511,:] ----
    dec_tokens_kernel<<<(BB*TT + 255)/256, 256>>>(tgts, dec_in);
    {
        long n = (long)BB*TT*EE;
        gather_kernel<<<(unsigned)((n + 255)/256), 256>>>(emb_dec, dec_embed, dec_in, (long)BB*TT, EE);
    }
    launch_gemm(1, 1, emb_dec, dec_rnn_Wih, dec_rnn_bih, nullptr, gi_dec,
                BB*TT, G3, EE, 0, 0, 0, 0, 1);
    gru_seq_kernel<<<4*BB, 128>>>(gi_dec, TT, dec_rnn_Whh, dec_rnn_bhh,
                                  enc2, (long)LS*HH, (long)(LS-1)*HH, dec_outb);

    // ---- decoder attention ----
    launch_gemm(1, 0, dec_outb, enc2, nullptr, nullptr, scores,
                TT, LS, HH, (long)TT*HH, (long)LS*HH, (long)TT*LS, 0, BB);
    softmax512<<<BB*TT, 256>>>(scores);
    launch_gemm(0, 0, scores, enc2, nullptr, nullptr, ctx,
                TT, HH, LS, (long)TT*LS, (long)LS*HH, (long)TT*HH, 0, BB);

    // ---- co = tanh([dec_out|ctx] @ Ww^T + bw) ----
    {
        long n = (long)BB*TT*2*HH;
        concat_kernel<<<(unsigned)((n + 255)/256), 256>>>(dec_outb, ctx, cat);
    }
    launch_gemm(1, 2, cat, Ww, bw, nullptr, co,
                BB*TT, HH, 2*HH, 0, 0, 0, 0, 1);

    // ---- logits = co @ Wp^T + bp (tf32 tensor cores), stored transposed into d_out ----
    {
        dim3 gr((VV + 127)/128, (BB*TT)/128, 1);
        logits_tf32_kernel<<<gr, 256>>>(co, Wp, bp, out, BB*TT, VV, HH);
    }

    // ---- loss ----
    nll_kernel<<<BB*TT, 256>>>(out, tgts, nll, valf);
    loss_reduce_kernel<<<1, 256>>>(nll, valf, out + OUT_LOSS);
}

// round 14
// speedup vs baseline: 1.8143x; 1.1591x over previous
#include <cuda_runtime.h>
#include <cooperative_groups.h>
#include <math.h>

namespace cg = cooperative_groups;

// ---------------- problem constants ----------------
#define BB   64      // batch
#define LS   512     // source length
#define LL   128     // law/legal length
#define TT   150     // target length
#define HH   150     // hidden
#define EE   200     // embed
#define G3   450     // 3*HH
#define VV   10000   // target vocab
#define NCH  62      // charges
#define SOS_TOK 2
#define EOS_TOK 1

#define OUT_LOSS   96000000L   // TT*BB*VV
#define OUT_CHARGE 96000001L

// ---------------- scratch (device globals; no allocation allowed) ----------------
__device__ float g_h0[BB*HH];
__device__ float g_emb_src[BB*LS*EE];
__device__ float g_gi[BB*LS*G3];
__device__ float g_enc_outs1[BB*LS*HH];
__device__ float g_chh[BB*HH];
__device__ int   g_legal_toks[BB*LL];
__device__ float g_emb_leg[BB*LL*EE];
__device__ float g_gi_leg[BB*LL*G3];
__device__ float g_legals[BB*LL*HH];
__device__ float g_att[BB*LS*LL];
__device__ float g_ca[BB*LS*HH];
__device__ float g_enc_outs[BB*LS*HH];
__device__ int   g_dec_in[BB*TT];
__device__ float g_emb_dec[BB*TT*EE];
__device__ float g_gi_dec[BB*TT*G3];
__device__ float g_dec_out[BB*TT*HH];
__device__ float g_scores[BB*TT*LS];
__device__ float g_ctx[BB*TT*HH];
__device__ float g_concat[BB*TT*2*HH];
__device__ float g_co[BB*TT*HH];
__device__ float g_nll[BB*TT];
__device__ float g_val[BB*TT];

// ---------------- small helpers ----------------
__device__ __forceinline__ float warp_max(float v){
    #pragma unroll
    for (int o=16;o;o>>=1) v = fmaxf(v, __shfl_xor_sync(0xffffffffu, v, o));
    return v;
}
__device__ __forceinline__ float warp_sum(float v){
    #pragma unroll
    for (int o=16;o;o>>=1) v += __shfl_xor_sync(0xffffffffu, v, o);
    return v;
}
template<int NW>
__device__ __forceinline__ float block_max(float v, float* red){
    v = warp_max(v);
    int w = threadIdx.x >> 5;
    if ((threadIdx.x & 31) == 0) red[w] = v;
    __syncthreads();
    float r = red[0];
    #pragma unroll
    for (int i=1;i<NW;i++) r = fmaxf(r, red[i]);
    __syncthreads();
    return r;
}
template<int NW>
__device__ __forceinline__ float block_sum(float v, float* red){
    v = warp_sum(v);
    int w = threadIdx.x >> 5;
    if ((threadIdx.x & 31) == 0) red[w] = v;
    __syncthreads();
    float r = red[0];
    #pragma unroll
    for (int i=1;i<NW;i++) r += red[i];
    __syncthreads();
    return r;
}

__device__ __forceinline__ uint32_t f2tf32(float f){
    uint32_t u;
    asm("cvt.rna.tf32.f32 %0, %1;" : "=r"(u) : "f"(f));
    return u;
}

// ---------------- trivial kernels ----------------
__global__ void zero_kernel(float* p, long n){
    long i = (long)blockIdx.x*blockDim.x + threadIdx.x;
    if (i < n) p[i] = 0.f;
}

__global__ void gather_kernel(float* __restrict__ out, const float* __restrict__ table,
                              const int* __restrict__ toks, long nrows, int E){
    long id = (long)blockIdx.x*blockDim.x + threadIdx.x;
    if (id < nrows*(long)E){
        long r = id / E; int j = (int)(id % E);
        out[id] = table[(long)toks[r]*E + j];
    }
}

__global__ void dec_tokens_kernel(const int* __restrict__ tgts, int* __restrict__ dec_in){
    int id = blockIdx.x*blockDim.x + threadIdx.x;
    if (id < BB*TT){
        int b = id / TT, t = id % TT;
        dec_in[id] = (t == 0) ? SOS_TOK : tgts[b*TT + t - 1];
    }
}

__global__ void mean_kernel(const float* __restrict__ outs1, float* __restrict__ chh){
    int b = blockIdx.x; int j = threadIdx.x;
    if (j < HH){
        float s = 0.f;
        for (int t=0;t<LS;t++) s += outs1[((long)b*LS + t)*HH + j];
        chh[b*HH + j] = s * (1.f/LS);
    }
}

__global__ void charge_kernel(const float* __restrict__ chh, const float* __restrict__ Wc,
                              const float* __restrict__ bc, const int* __restrict__ law_tokens,
                              float* __restrict__ out_charge, int* __restrict__ legal_toks){
    int b = blockIdx.x; int tid = threadIdx.x;   // 128 threads
    __shared__ float h[HH];
    __shared__ float sc[NCH];
    __shared__ int cid;
    for (int i=tid;i<HH;i+=128) h[i] = chh[b*HH + i];
    __syncthreads();
    if (tid < NCH){
        float a = bc[tid];
        const float* w = Wc + tid*HH;
        for (int k=0;k<HH;k++) a += h[k]*w[k];
        sc[tid] = a;
        out_charge[b*NCH + tid] = a;
    }
    __syncthreads();
    if (tid == 0){
        int best = 0; float bv = sc[0];
        for (int c=1;c<NCH;c++) if (sc[c] > bv){ bv = sc[c]; best = c; }
        cid = best;
    }
    __syncthreads();
    for (int i=tid;i<LL;i+=128) legal_toks[b*LL + i] = law_tokens[cid*LL + i];
}

// ---------------- persistent GRU sequence kernel: 4-CTA cluster per batch row --------
// (R11 configuration — best measured. cluster.sync per step; both mbarrier-handshake
//  variants regressed. Frozen.)
__global__ void __cluster_dims__(4,1,1) __launch_bounds__(128,2)
gru_seq_kernel(const float* __restrict__ gi, int T,
               const float* __restrict__ Whh, const float* __restrict__ bhh,
               const float* __restrict__ hinit, long hi_stride, long hi_off,
               float* __restrict__ out)
{
    cg::cluster_group cluster = cg::this_cluster();
    int rank = cluster.block_rank();            // 0..3
    int b = blockIdx.x >> 2;                    // batch row
    int tid = threadIdx.x;

    __shared__ float h_sm[2][152];   // full h, padded for float4
    __shared__ float sg[3][40];      // this CTA's gate partials

    int nj = (rank < 3) ? 38 : 36;   // 150 = 38+38+38+36
    int gate = tid / 38;             // 0..2 for tid<114
    int jj = tid - gate*38;
    bool act = (tid < 114) && (jj < nj);
    int j = rank*38 + jj;            // gate-row hidden index
    int grow = act ? (gate*HH + j) : 0;

    // register-resident weight row (padded with zeros to 152)
    float w[152];
    if (act){
        #pragma unroll
        for (int k=0;k<150;k++) w[k] = Whh[(long)grow*HH + k];
        w[150] = 0.f; w[151] = 0.f;
    } else {
        #pragma unroll
        for (int k=0;k<152;k++) w[k] = 0.f;
    }
    float bias = act ? bhh[grow] : 0.f;

    // init h buffers
    for (int k=tid;k<152;k+=128){
        h_sm[0][k] = (k < HH) ? hinit[(long)b*hi_stride + hi_off + k] : 0.f;
        h_sm[1][k] = 0.f;
    }

    // mapped h pointers for all 4 CTAs of the cluster (incl. self)
    float* ph0 = (float*)cluster.map_shared_rank((void*)&h_sm[0][0], 0);
    float* ph1 = (float*)cluster.map_shared_rank((void*)&h_sm[0][0], 1);
    float* ph2 = (float*)cluster.map_shared_rank((void*)&h_sm[0][0], 2);
    float* ph3 = (float*)cluster.map_shared_rank((void*)&h_sm[0][0], 3);

    cluster.sync();   // init visible before any peer writes

    int p = 0;
    for (int t=0;t<T;t++){
        // prefetch gi for the combine threads (overlaps the matvec)
        float gr = 0.f, gz = 0.f, gn = 0.f;
        int jc = rank*38 + tid;
        if (tid < nj){
            const float* g = gi + ((long)b*T + t)*G3;
            gr = g[jc]; gz = g[HH + jc]; gn = g[2*HH + jc];
        }

        if (tid < 114){   // padded rows compute zeros into unused sg slots
            const float4* h4 = (const float4*)&h_sm[p][0];
            float a0 = 0.f, a1 = 0.f, a2 = 0.f, a3 = 0.f;
            #pragma unroll
            for (int k4=0;k4<38;k4++){
                float4 hv = h4[k4];
                a0 += w[4*k4+0]*hv.x;
                a1 += w[4*k4+1]*hv.y;
                a2 += w[4*k4+2]*hv.z;
                a3 += w[4*k4+3]*hv.w;
            }
            sg[gate][jj] = (a0 + a1) + (a2 + a3) + bias;
        }
        __syncthreads();

        if (tid < nj){
            float r = 1.f/(1.f + expf(-(gr + sg[0][tid])));
            float z = 1.f/(1.f + expf(-(gz + sg[1][tid])));
            float n = tanhf(gn + r*sg[2][tid]);
            float hp = h_sm[p][jc];
            float hn = (1.f - z)*n + z*hp;
            int dst = (1-p)*152 + jc;
            ph0[dst] = hn;                      // broadcast to all 4 CTAs (DSMEM)
            ph1[dst] = hn;
            ph2[dst] = hn;
            ph3[dst] = hn;
            out[((long)b*T + t)*HH + jc] = hn;
        }
        cluster.sync();   // all CTAs' h slices visible everywhere; orders sg reuse
        p ^= 1;
    }
}

// ---------------- fp32 tiled SGEMM (pre-charge path only; keeps charge argmax bit-exact)
// EPI: 0=plain, 1=+bias, 2=tanh(+bias), 3=+residual
template<int TRANSB, int EPI>
__global__ void gemm_kernel(const float* __restrict__ A, const float* __restrict__ Bm,
                            const float* __restrict__ bias, const float* __restrict__ res,
                            float* __restrict__ C,
                            int M, int N, int K,
                            long sA, long sB, long sC, long sR){
    int z = blockIdx.z;
    A  += (long)z*sA;
    Bm += (long)z*sB;
    C  += (long)z*sC;
    const float* R = (EPI==3) ? (res + (long)z*sR) : res;

    int m0 = blockIdx.y*64, n0 = blockIdx.x*64;
    __shared__ float As[16][68];
    __shared__ float Bs[16][68];
    int tid = threadIdx.x;
    int tx = tid & 15, ty = tid >> 4;
    float c[4][4] = {};

    for (int kk=0; kk<K; kk+=16){
        for (int idx=tid; idx<64*16; idx+=256){
            int i = idx >> 4, k = idx & 15;
            int mi = m0 + i, ki = kk + k;
            As[k][i] = (mi < M && ki < K) ? A[(long)mi*K + ki] : 0.f;
        }
        if (TRANSB){
            for (int idx=tid; idx<64*16; idx+=256){
                int j = idx >> 4, k = idx & 15;
                int nj = n0 + j, ki = kk + k;
                Bs[k][j] = (nj < N && ki < K) ? Bm[(long)nj*K + ki] : 0.f;
            }
        } else {
            for (int idx=tid; idx<64*16; idx+=256){
                int j = idx & 63, k = idx >> 6;
                int nj = n0 + j, ki = kk + k;
                Bs[k][j] = (nj < N && ki < K) ? Bm[(long)ki*N + nj] : 0.f;
            }
        }
        __syncthreads();
        #pragma unroll
        for (int k=0;k<16;k++){
            float4 a4 = *(const float4*)&As[k][ty*4];
            float4 b4 = *(const float4*)&Bs[k][tx*4];
            float af[4] = {a4.x,a4.y,a4.z,a4.w};
            float bf[4] = {b4.x,b4.y,b4.z,b4.w};
            #pragma unroll
            for (int r=0;r<4;r++)
                #pragma unroll
                for (int cc=0;cc<4;cc++)
                    c[r][cc] += af[r]*bf[cc];
        }
        __syncthreads();
    }

    #pragma unroll
    for (int r=0;r<4;r++){
        int i = m0 + ty*4 + r;
        if (i >= M) continue;
        #pragma unroll
        for (int cc=0;cc<4;cc++){
            int j = n0 + tx*4 + cc;
            if (j >= N) continue;
            float v = c[r][cc];
            if (EPI==1 || EPI==2) v += bias[j];
            if (EPI==2) v = tanhf(v);
            if (EPI==3) v += R[(long)i*N + j];
            C[(long)i*N + j] = v;
        }
    }
}

// ---------------- tf32 tensor-core batched GEMM: 64x64 tile -------------------------
// C = A[M,K] x (TRANSB ? B[N,K]^T : B[K,N]) with EPI 0/1/2/3 as above.
// 256 threads = 8 warps (2M x 4N), warp tile 32x16, mma.m16n8k8 tf32/fp32-acc.
// smem stride 72 (== 8 mod 32) -> conflict-free fragment LDS (same argument as the
// logits kernel's stride 136). Fragment mapping identical to the validated logits kernel.
#define ST72 72
template<int TRANSB, int EPI>
__global__ void __launch_bounds__(256)
gemm_tf32_kernel(const float* __restrict__ A, const float* __restrict__ Bm,
                 const float* __restrict__ bias, const float* __restrict__ res,
                 float* __restrict__ C,
                 int M, int N, int K,
                 long sA, long sB, long sC, long sR){
    int z = blockIdx.z;
    A  += (long)z*sA;
    Bm += (long)z*sB;
    C  += (long)z*sC;
    const float* R = (EPI==3) ? (res + (long)z*sR) : res;

    __shared__ float As[16*ST72];
    __shared__ float Bs[16*ST72];
    int m0 = blockIdx.y*64, n0 = blockIdx.x*64;
    int tid = threadIdx.x;
    int lane = tid & 31, warp = tid >> 5;
    int wm = warp >> 2, wn = warp & 3;      // 2 x 4 warp grid
    int g = lane >> 2, t4 = lane & 3;

    float c[2][2][4];
    #pragma unroll
    for (int a=0;a<2;a++)
        #pragma unroll
        for (int bq=0;bq<2;bq++)
            #pragma unroll
            for (int r=0;r<4;r++) c[a][bq][r] = 0.f;

    for (int kk=0; kk<K; kk+=16){
        #pragma unroll
        for (int l=0;l<4;l++){
            int idx = tid + l*256;
            int i = idx >> 4, k = idx & 15;
            int mi = m0 + i, ki = kk + k;
            As[k*ST72 + i] = (mi < M && ki < K) ? A[(long)mi*K + ki] : 0.f;
        }
        if (TRANSB){
            #pragma unroll
            for (int l=0;l<4;l++){
                int idx = tid + l*256;
                int j = idx >> 4, k = idx & 15;
                int nj = n0 + j, ki = kk + k;
                Bs[k*ST72 + j] = (nj < N && ki < K) ? Bm[(long)nj*K + ki] : 0.f;
            }
        } else {
            #pragma unroll
            for (int l=0;l<4;l++){
                int idx = tid + l*256;
                int j = idx & 63, k = idx >> 6;
                int nj = n0 + j, ki = kk + k;
                Bs[k*ST72 + j] = (nj < N && ki < K) ? Bm[(long)ki*N + nj] : 0.f;
            }
        }
        __syncthreads();
        #pragma unroll
        for (int k8=0;k8<16;k8+=8){
            uint32_t bf[2][2];
            #pragma unroll
            for (int nt=0;nt<2;nt++){
                int nb = wn*16 + nt*8 + g;
                bf[nt][0] = f2tf32(Bs[(k8+t4)*ST72 + nb]);
                bf[nt][1] = f2tf32(Bs[(k8+t4+4)*ST72 + nb]);
            }
            #pragma unroll
            for (int mt=0;mt<2;mt++){
                int mb = wm*32 + mt*16 + g;
                uint32_t a0 = f2tf32(As[(k8+t4)*ST72 + mb]);
                uint32_t a1 = f2tf32(As[(k8+t4)*ST72 + mb + 8]);
                uint32_t a2 = f2tf32(As[(k8+t4+4)*ST72 + mb]);
                uint32_t a3 = f2tf32(As[(k8+t4+4)*ST72 + mb + 8]);
                #pragma unroll
                for (int nt=0;nt<2;nt++){
                    asm volatile(
                        "mma.sync.aligned.m16n8k8.row.col.f32.tf32.tf32.f32 "
                        "{%0,%1,%2,%3}, {%4,%5,%6,%7}, {%8,%9}, {%0,%1,%2,%3};"
                        : "+f"(c[mt][nt][0]), "+f"(c[mt][nt][1]),
                          "+f"(c[mt][nt][2]), "+f"(c[mt][nt][3])
                        : "r"(a0), "r"(a1), "r"(a2), "r"(a3),
                          "r"(bf[nt][0]), "r"(bf[nt][1]));
                }
            }
        }
        __syncthreads();
    }

    // epilogue: c0:(g,2t4) c1:(g,2t4+1) c2:(g+8,2t4) c3:(g+8,2t4+1)
    #pragma unroll
    for (int mt=0;mt<2;mt++){
        int i0 = m0 + wm*32 + mt*16 + g;
        #pragma unroll
        for (int nt=0;nt<2;nt++){
            int j0 = n0 + wn*16 + nt*8 + t4*2;
            #pragma unroll
            for (int rr=0;rr<2;rr++){
                int i = i0 + rr*8;
                if (i >= M) continue;
                #pragma unroll
                for (int cc2=0;cc2<2;cc2++){
                    int j = j0 + cc2;
                    if (j >= N) continue;
                    float v = c[mt][nt][rr*2 + cc2];
                    if (EPI==1 || EPI==2) v += bias[j];
                    if (EPI==2) v = tanhf(v);
                    if (EPI==3) v += R[(long)i*N + j];
                    C[(long)i*N + j] = v;
                }
            }
        }
    }
}

// ---------------- tf32 tensor-core GEMM for logits (128x128 tile, transposed store) ----
#define TFST 136
__global__ void __launch_bounds__(256)
logits_tf32_kernel(const float* __restrict__ A, const float* __restrict__ Bm,
                   const float* __restrict__ bias, float* __restrict__ C,
                   int M, int N, int K){
    __shared__ float As[16*TFST];
    __shared__ float Bs[16*TFST];
    int m0 = blockIdx.y*128, n0 = blockIdx.x*128;
    int tid = threadIdx.x;
    int lane = tid & 31, warp = tid >> 5;
    int wm = warp >> 2, wn = warp & 3;      // 2 x 4 warp grid
    int g = lane >> 2, t4 = lane & 3;

    float c[4][4][4];
    #pragma unroll
    for (int a=0;a<4;a++)
        #pragma unroll
        for (int bq=0;bq<4;bq++)
            #pragma unroll
            for (int r=0;r<4;r++) c[a][bq][r] = 0.f;

    for (int kk=0; kk<K; kk+=16){
        #pragma unroll
        for (int l=0;l<8;l++){
            int idx = tid + l*256;
            int i = idx >> 4, k = idx & 15;
            int ki = kk + k;
            As[k*TFST + i] = (ki < K) ? A[(long)(m0+i)*K + ki] : 0.f;  // M % 128 == 0
            int nj = n0 + i;
            Bs[k*TFST + i] = (nj < N && ki < K) ? Bm[(long)nj*K + ki] : 0.f;
        }
        __syncthreads();
        #pragma unroll
        for (int k8=0;k8<16;k8+=8){
            uint32_t bf[4][2];
            #pragma unroll
            for (int nt=0;nt<4;nt++){
                int nb = wn*32 + nt*8 + g;
                bf[nt][0] = f2tf32(Bs[(k8+t4)*TFST + nb]);
                bf[nt][1] = f2tf32(Bs[(k8+t4+4)*TFST + nb]);
            }
            #pragma unroll
            for (int mt=0;mt<4;mt++){
                int mb = wm*64 + mt*16 + g;
                uint32_t a0 = f2tf32(As[(k8+t4)*TFST + mb]);
                uint32_t a1 = f2tf32(As[(k8+t4)*TFST + mb + 8]);
                uint32_t a2 = f2tf32(As[(k8+t4+4)*TFST + mb]);
                uint32_t a3 = f2tf32(As[(k8+t4+4)*TFST + mb + 8]);
                #pragma unroll
                for (int nt=0;nt<4;nt++){
                    asm volatile(
                        "mma.sync.aligned.m16n8k8.row.col.f32.tf32.tf32.f32 "
                        "{%0,%1,%2,%3}, {%4,%5,%6,%7}, {%8,%9}, {%0,%1,%2,%3};"
                        : "+f"(c[mt][nt][0]), "+f"(c[mt][nt][1]),
                          "+f"(c[mt][nt][2]), "+f"(c[mt][nt][3])
                        : "r"(a0), "r"(a1), "r"(a2), "r"(a3),
                          "r"(bf[nt][0]), "r"(bf[nt][1]));
                }
            }
        }
        __syncthreads();
    }

    #pragma unroll
    for (int mt=0;mt<4;mt++){
        int i0 = m0 + wm*64 + mt*16 + g;
        #pragma unroll
        for (int nt=0;nt<4;nt++){
            int j0 = n0 + wn*32 + nt*8 + t4*2;
            #pragma unroll
            for (int rr=0;rr<2;rr++){
                int i = i0 + rr*8;
                int bb2 = i / TT, tt2 = i % TT;
                long rowoff = ((long)(tt2*BB + bb2))*N;
                #pragma unroll
                for (int cc2=0;cc2<2;cc2++){
                    int j = j0 + cc2;
                    if (j < N)
                        C[rowoff + j] = c[mt][nt][rr*2 + cc2] + bias[j];
                }
            }
        }
    }
}

// ---------------- softmaxes ----------------
__global__ void mask_softmax128(float* __restrict__ att){
    long row = blockIdx.x;
    int tid = threadIdx.x;  // 128 threads
    __shared__ float red[4];
    float x = att[row*LL + tid];
    float xm = (x == 0.f) ? -INFINITY : x;
    float M = block_max<4>(xm, red);
    float e = isinf(M) ? 0.f : expf(xm - M);
    float S = block_sum<4>(e, red);
    att[row*LL + tid] = (S > 0.f) ? e / S : 0.f;
}

__global__ void softmax512(float* __restrict__ x){
    long row = blockIdx.x;
    int tid = threadIdx.x;
    __shared__ float red[8];
    float* p = x + row*(long)LS;
    float v0 = p[tid], v1 = p[tid + 256];
    float M = block_max<8>(fmaxf(v0, v1), red);
    float e0 = expf(v0 - M), e1 = expf(v1 - M);
    float S = block_sum<8>(e0 + e1, red);
    float inv = 1.f / S;
    p[tid] = e0*inv; p[tid + 256] = e1*inv;
}

__global__ void concat_kernel(const float* __restrict__ dec_out, const float* __restrict__ ctx,
                              float* __restrict__ cat){
    long id = (long)blockIdx.x*blockDim.x + threadIdx.x;
    long n = (long)BB*TT*2*HH;
    if (id < n){
        long m = id / (2*HH); int j = (int)(id % (2*HH));
        cat[id] = (j < HH) ? dec_out[m*HH + j] : ctx[m*HH + (j - HH)];
    }
}

__global__ void nll_kernel(const float* __restrict__ logits_out, const int* __restrict__ tgts,
                           float* __restrict__ nll, float* __restrict__ validf){
    int row = blockIdx.x;           // b*TT + t
    int tid = threadIdx.x;          // 256 threads
    int b = row / TT, t = row % TT;
    const float* x = logits_out + ((long)(t*BB + b))*VV;
    __shared__ float red[8];
    float m = -INFINITY;
    for (int i=tid;i<VV;i+=256) m = fmaxf(m, x[i]);
    float M = block_max<8>(m, red);
    float s = 0.f;
    for (int i=tid;i<VV;i+=256) s += expf(x[i] - M);
    float S = block_sum<8>(s, red);
    if (tid == 0){
        int tg = tgts[row];
        float v = (tg != EOS_TOK) ? 1.f : 0.f;
        nll[row] = v * ((M + logf(S)) - x[tg]);
        validf[row] = v;
    }
}

__global__ void loss_reduce_kernel(const float* __restrict__ nll, const float* __restrict__ val,
                                   float* __restrict__ out_loss){
    __shared__ float red[8];
    int t = threadIdx.x;  // 256 threads
    float v = 0.f;
    if (t < TT){
        float s = 0.f, c = 0.f;
        for (int b=0;b<BB;b++){ s += nll[b*TT + t]; c += val[b*TT + t]; }
        v = s / fmaxf(c, 1.f);
    }
    float tot = block_sum<8>(v, red);
    if (t == 0) out_loss[0] = tot;
}

// ---------------- host side ----------------
static void launch_gemm_f32(int transb, int epi,
                            const float* A, const float* Bm, const float* bias, const float* res,
                            float* C, int M, int N, int K,
                            long sA, long sB, long sC, long sR, int batch){
    dim3 gr((N + 63)/64, (M + 63)/64, batch);
    dim3 bl(256);
    if (transb){
        if (epi == 0)      gemm_kernel<1,0><<<gr,bl>>>(A,Bm,bias,res,C,M,N,K,sA,sB,sC,sR);
        else if (epi == 1) gemm_kernel<1,1><<<gr,bl>>>(A,Bm,bias,res,C,M,N,K,sA,sB,sC,sR);
        else               gemm_kernel<1,2><<<gr,bl>>>(A,Bm,bias,res,C,M,N,K,sA,sB,sC,sR);
    } else {
        if (epi == 0)      gemm_kernel<0,0><<<gr,bl>>>(A,Bm,bias,res,C,M,N,K,sA,sB,sC,sR);
        else               gemm_kernel<0,3><<<gr,bl>>>(A,Bm,bias,res,C,M,N,K,sA,sB,sC,sR);
    }
}

static void launch_gemm_tf32(int transb, int epi,
                             const float* A, const float* Bm, const float* bias, const float* res,
                             float* C, int M, int N, int K,
                             long sA, long sB, long sC, long sR, int batch){
    dim3 gr((N + 63)/64, (M + 63)/64, batch);
    dim3 bl(256);
    if (transb){
        if (epi == 0)      gemm_tf32_kernel<1,0><<<gr,bl>>>(A,Bm,bias,res,C,M,N,K,sA,sB,sC,sR);
        else if (epi == 1) gemm_tf32_kernel<1,1><<<gr,bl>>>(A,Bm,bias,res,C,M,N,K,sA,sB,sC,sR);
        else               gemm_tf32_kernel<1,2><<<gr,bl>>>(A,Bm,bias,res,C,M,N,K,sA,sB,sC,sR);
    } else {
        if (epi == 0)      gemm_tf32_kernel<0,0><<<gr,bl>>>(A,Bm,bias,res,C,M,N,K,sA,sB,sC,sR);
        else               gemm_tf32_kernel<0,3><<<gr,bl>>>(A,Bm,bias,res,C,M,N,K,sA,sB,sC,sR);
    }
}

template<typename T> static T* sym(const void* s){
    void* p = nullptr;
    cudaGetSymbolAddress(&p, s);
    return (T*)p;
}

extern "C" void kernel_launch(void* const* d_in, const int* in_sizes, int n_in,
                              void* d_out, int out_size){
    const int*   srcs        = (const int*)  d_in[0];
    const int*   tgts        = (const int*)  d_in[1];
    const int*   law_tokens  = (const int*)  d_in[2];
    const float* src_embed   = (const float*)d_in[3];
    const float* enc_rnn_Wih = (const float*)d_in[4];
    const float* enc_rnn_Whh = (const float*)d_in[5];
    const float* enc_rnn_bih = (const float*)d_in[6];
    const float* enc_rnn_bhh = (const float*)d_in[7];
    const float* enc_gru_Wih = (const float*)d_in[8];
    const float* enc_gru_Whh = (const float*)d_in[9];
    const float* enc_gru_bih = (const float*)d_in[10];
    const float* enc_gru_bhh = (const float*)d_in[11];
    const float* dec_embed   = (const float*)d_in[12];
    const float* dec_rnn_Wih = (const float*)d_in[13];
    const float* dec_rnn_Whh = (const float*)d_in[14];
    const float* dec_rnn_bih = (const float*)d_in[15];
    const float* dec_rnn_bhh = (const float*)d_in[16];
    const float* Ww          = (const float*)d_in[17];
    const float* bw          = (const float*)d_in[18];
    const float* Wp          = (const float*)d_in[19];
    const float* bp          = (const float*)d_in[20];
    const float* Wc          = (const float*)d_in[21];
    const float* bc          = (const float*)d_in[22];
    float* out = (float*)d_out;

    float* h0       = sym<float>(g_h0);
    float* emb_src  = sym<float>(g_emb_src);
    float* gi       = sym<float>(g_gi);
    float* enc1     = sym<float>(g_enc_outs1);
    float* chh      = sym<float>(g_chh);
    int*   leg_toks = sym<int>(g_legal_toks);
    float* emb_leg  = sym<float>(g_emb_leg);
    float* gi_leg   = sym<float>(g_gi_leg);
    float* legals   = sym<float>(g_legals);
    float* att      = sym<float>(g_att);
    float* ca       = sym<float>(g_ca);
    float* enc2     = sym<float>(g_enc_outs);
    int*   dec_in   = sym<int>(g_dec_in);
    float* emb_dec  = sym<float>(g_emb_dec);
    float* gi_dec   = sym<float>(g_gi_dec);
    float* dec_outb = sym<float>(g_dec_out);
    float* scores   = sym<float>(g_scores);
    float* ctx      = sym<float>(g_ctx);
    float* cat      = sym<float>(g_concat);
    float* co       = sym<float>(g_co);
    float* nll      = sym<float>(g_nll);
    float* valf     = sym<float>(g_val);

    // h0 = zeros
    zero_kernel<<<(BB*HH + 255)/256, 256>>>(h0, BB*HH);

    // ---- encoder pass 1 (fp32: feeds charge argmax — must stay bit-identical) ----
    {
        long n = (long)BB*LS*EE;
        gather_kernel<<<(unsigned)((n + 255)/256), 256>>>(emb_src, src_embed, srcs, (long)BB*LS, EE);
    }
    launch_gemm_f32(1, 1, emb_src, enc_rnn_Wih, enc_rnn_bih, nullptr, gi,
                    BB*LS, G3, EE, 0, 0, 0, 0, 1);
    gru_seq_kernel<<<4*BB, 128>>>(gi, LS, enc_rnn_Whh, enc_rnn_bhh, h0, HH, 0, enc1);

    // ---- charge prediction + legal tokens (fp32) ----
    mean_kernel<<<BB, 160>>>(enc1, chh);
    charge_kernel<<<BB, 128>>>(chh, Wc, bc, law_tokens, out + OUT_CHARGE, leg_toks);

    // ---- legal encoding (post-argmax: tf32 safe) ----
    {
        long n = (long)BB*LL*EE;
        gather_kernel<<<(unsigned)((n + 255)/256), 256>>>(emb_leg, src_embed, leg_toks, (long)BB*LL, EE);
    }
    launch_gemm_tf32(1, 1, emb_leg, enc_rnn_Wih, enc_rnn_bih, nullptr, gi_leg,
                     BB*LL, G3, EE, 0, 0, 0, 0, 1);
    gru_seq_kernel<<<4*BB, 128>>>(gi_leg, LL, enc_rnn_Whh, enc_rnn_bhh, h0, HH, 0, legals);

    // ---- mask attention (tf32): att = enc1 @ legals^T, masked softmax, ca = aw@legals + enc1 ----
    launch_gemm_tf32(1, 0, enc1, legals, nullptr, nullptr, att,
                     LS, LL, HH, (long)LS*HH, (long)LL*HH, (long)LS*LL, 0, BB);
    mask_softmax128<<<BB*LS, 128>>>(att);
    launch_gemm_tf32(0, 3, att, legals, nullptr, enc1, ca,
                     LS, HH, LL, (long)LS*LL, (long)LL*HH, (long)LS*HH, (long)LS*HH, BB);

    // ---- encoder pass 2 (tf32 gi) ----
    launch_gemm_tf32(1, 1, ca, enc_gru_Wih, enc_gru_bih, nullptr, gi,
                     BB*LS, G3, HH, 0, 0, 0, 0, 1);
    gru_seq_kernel<<<4*BB, 128>>>(gi, LS, enc_gru_Whh, enc_gru_bhh, h0, HH, 0, enc2);

    // ---- decoder GRU (teacher forcing, tf32 gi), h0 = enc2[:,511,:] ----
    dec_tokens_kernel<<<(BB*TT + 255)/256, 256>>>(tgts, dec_in);
    {
        long n = (long)BB*TT*EE;
        gather_kernel<<<(unsigned)((n + 255)/256), 256>>>(emb_dec, dec_embed, dec_in, (long)BB*TT, EE);
    }
    launch_gemm_tf32(1, 1, emb_dec, dec_rnn_Wih, dec_rnn_bih, nullptr, gi_dec,
                     BB*TT, G3, EE, 0, 0, 0, 0, 1);
    gru_seq_kernel<<<4*BB, 128>>>(gi_dec, TT, dec_rnn_Whh, dec_rnn_bhh,
                                  enc2, (long)LS*HH, (long)(LS-1)*HH, dec_outb);

    // ---- decoder attention (tf32) ----
    launch_gemm_tf32(1, 0, dec_outb, enc2, nullptr, nullptr, scores,
                     TT, LS, HH, (long)TT*HH, (long)LS*HH, (long)TT*LS, 0, BB);
    softmax512<<<BB*TT, 256>>>(scores);
    launch_gemm_tf32(0, 0, scores, enc2, nullptr, nullptr, ctx,
                     TT, HH, LS, (long)TT*LS, (long)LS*HH, (long)TT*HH, 0, BB);

    // ---- co = tanh([dec_out|ctx] @ Ww^T + bw) (tf32) ----
    {
        long n = (long)BB*TT*2*HH;
        concat_kernel<<<(unsigned)((n + 255)/256), 256>>>(dec_outb, ctx, cat);
    }
    launch_gemm_tf32(1, 2, cat, Ww, bw, nullptr, co,
                     BB*TT, HH, 2*HH, 0, 0, 0, 0, 1);

    // ---- logits = co @ Wp^T + bp (tf32 tensor cores), stored transposed into d_out ----
    {
        dim3 gr((VV + 127)/128, (BB*TT)/128, 1);
        logits_tf32_kernel<<<gr, 256>>>(co, Wp, bp, out, BB*TT, VV, HH);
    }

    // ---- loss ----
    nll_kernel<<<BB*TT, 256>>>(out, tgts, nll, valf);
    loss_reduce_kernel<<<1, 256>>>(nll, valf, out + OUT_LOSS);
}

// round 16
// speedup vs baseline: 1.8363x; 1.0121x over previous
#include <cuda_runtime.h>
#include <cooperative_groups.h>
#include <math.h>

namespace cg = cooperative_groups;

// ---------------- problem constants ----------------
#define BB   64      // batch
#define LS   512     // source length
#define LL   128     // law/legal length
#define TT   150     // target length
#define HH   150     // hidden
#define EE   200     // embed
#define G3   450     // 3*HH
#define VV   10000   // target vocab
#define NCH  62      // charges
#define SOS_TOK 2
#define EOS_TOK 1

#define OUT_LOSS   96000000L   // TT*BB*VV
#define OUT_CHARGE 96000001L

// ---------------- scratch (device globals; no allocation allowed) ----------------
__device__ float g_h0[BB*HH];
__device__ float g_emb_src[BB*LS*EE];
__device__ float g_gi[BB*LS*G3];
__device__ float g_enc_outs1[BB*LS*HH];
__device__ float g_chh[BB*HH];
__device__ int   g_legal_toks[BB*LL];
__device__ float g_emb_leg[BB*LL*EE];
__device__ float g_gi_leg[BB*LL*G3];
__device__ float g_legals[BB*LL*HH];
__device__ float g_att[BB*LS*LL];
__device__ float g_ca[BB*LS*HH];
__device__ float g_enc_outs[BB*LS*HH];
__device__ int   g_dec_in[BB*TT];
__device__ float g_emb_dec[BB*TT*EE];
__device__ float g_gi_dec[BB*TT*G3];
__device__ float g_dec_out[BB*TT*HH];
__device__ float g_scores[BB*TT*LS];
__device__ float g_ctx[BB*TT*HH];
__device__ float g_concat[BB*TT*2*HH];
__device__ float g_co[BB*TT*HH];
__device__ float g_nll[BB*TT];
__device__ float g_val[BB*TT];

// ---------------- small helpers ----------------
__device__ __forceinline__ float warp_max(float v){
    #pragma unroll
    for (int o=16;o;o>>=1) v = fmaxf(v, __shfl_xor_sync(0xffffffffu, v, o));
    return v;
}
__device__ __forceinline__ float warp_sum(float v){
    #pragma unroll
    for (int o=16;o;o>>=1) v += __shfl_xor_sync(0xffffffffu, v, o);
    return v;
}
template<int NW>
__device__ __forceinline__ float block_max(float v, float* red){
    v = warp_max(v);
    int w = threadIdx.x >> 5;
    if ((threadIdx.x & 31) == 0) red[w] = v;
    __syncthreads();
    float r = red[0];
    #pragma unroll
    for (int i=1;i<NW;i++) r = fmaxf(r, red[i]);
    __syncthreads();
    return r;
}
template<int NW>
__device__ __forceinline__ float block_sum(float v, float* red){
    v = warp_sum(v);
    int w = threadIdx.x >> 5;
    if ((threadIdx.x & 31) == 0) red[w] = v;
    __syncthreads();
    float r = red[0];
    #pragma unroll
    for (int i=1;i<NW;i++) r += red[i];
    __syncthreads();
    return r;
}

__device__ __forceinline__ uint32_t f2tf32(float f){
    uint32_t u;
    asm("cvt.rna.tf32.f32 %0, %1;" : "=r"(u) : "f"(f));
    return u;
}

// fast sigmoid / tanh via MUFU (__expf rel err ~1e-7; clamped against overflow)
__device__ __forceinline__ float fast_sigmoid(float x){
    x = fminf(fmaxf(x, -30.f), 30.f);
    return __fdividef(1.f, 1.f + __expf(-x));
}
__device__ __forceinline__ float fast_tanh(float x){
    x = fminf(fmaxf(x, -15.f), 15.f);
    float e = __expf(2.f*x);
    return __fdividef(e - 1.f, e + 1.f);
}

// ---------------- trivial kernels ----------------
__global__ void zero_kernel(float* p, long n){
    long i = (long)blockIdx.x*blockDim.x + threadIdx.x;
    if (i < n) p[i] = 0.f;
}

__global__ void gather_kernel(float* __restrict__ out, const float* __restrict__ table,
                              const int* __restrict__ toks, long nrows, int E){
    long id = (long)blockIdx.x*blockDim.x + threadIdx.x;
    if (id < nrows*(long)E){
        long r = id / E; int j = (int)(id % E);
        out[id] = table[(long)toks[r]*E + j];
    }
}

__global__ void dec_tokens_kernel(const int* __restrict__ tgts, int* __restrict__ dec_in){
    int id = blockIdx.x*blockDim.x + threadIdx.x;
    if (id < BB*TT){
        int b = id / TT, t = id % TT;
        dec_in[id] = (t == 0) ? SOS_TOK : tgts[b*TT + t - 1];
    }
}

__global__ void mean_kernel(const float* __restrict__ outs1, float* __restrict__ chh){
    int b = blockIdx.x; int j = threadIdx.x;
    if (j < HH){
        float s = 0.f;
        for (int t=0;t<LS;t++) s += outs1[((long)b*LS + t)*HH + j];
        chh[b*HH + j] = s * (1.f/LS);
    }
}

__global__ void charge_kernel(const float* __restrict__ chh, const float* __restrict__ Wc,
                              const float* __restrict__ bc, const int* __restrict__ law_tokens,
                              float* __restrict__ out_charge, int* __restrict__ legal_toks){
    int b = blockIdx.x; int tid = threadIdx.x;   // 128 threads
    __shared__ float h[HH];
    __shared__ float sc[NCH];
    __shared__ int cid;
    for (int i=tid;i<HH;i+=128) h[i] = chh[b*HH + i];
    __syncthreads();
    if (tid < NCH){
        float a = bc[tid];
        const float* w = Wc + tid*HH;
        for (int k=0;k<HH;k++) a += h[k]*w[k];
        sc[tid] = a;
        out_charge[b*NCH + tid] = a;
    }
    __syncthreads();
    if (tid == 0){
        int best = 0; float bv = sc[0];
        for (int c=1;c<NCH;c++) if (sc[c] > bv){ bv = sc[c]; best = c; }
        cid = best;
    }
    __syncthreads();
    for (int i=tid;i<LL;i+=128) legal_toks[b*LL + i] = law_tokens[cid*LL + i];
}

// ---------------- persistent GRU sequence kernel: 4-CTA cluster per batch row --------
// R11 sync structure (cluster.sync per step — frozen). R15 changes INSIDE the step:
//  * split-K matvec: 2 threads per gate row, 76 h-elements each (19 float4 loads,
//    19-deep FFMA chains — half the dependency depth), pair-sum via shfl_xor(1).
//    Block 256, __launch_bounds__(256,2): 2 CTAs/SM -> 16 warps/SM hides latency.
//  * fast sigmoid/tanh in the combine (__expf/__fdividef, ~1e-6 rel err).
__global__ void __cluster_dims__(4,1,1) __launch_bounds__(256,2)
gru_seq_kernel(const float* __restrict__ gi, int T,
               const float* __restrict__ Whh, const float* __restrict__ bhh,
               const float* __restrict__ hinit, long hi_stride, long hi_off,
               float* __restrict__ out)
{
    cg::cluster_group cluster = cg::this_cluster();
    int rank = cluster.block_rank();            // 0..3
    int b = blockIdx.x >> 2;                    // batch row
    int tid = threadIdx.x;

    __shared__ float h_sm[2][152];   // full h, padded for float4
    __shared__ float sg[3][40];      // this CTA's gate partials

    int nj = (rank < 3) ? 38 : 36;   // 150 = 38+38+38+36

    // matvec mapping: 2 threads per gate row; pairs (2r, 2r+1) share a warp
    int row = tid >> 1;              // 0..127
    int half = tid & 1;              // K-half: [0,76) or [76,152)
    int gate = row / 38;             // 0..2 valid; 3 = padding rows
    int jj = row - gate*38;
    bool act = (gate < 3) && (jj < nj);
    int j = rank*38 + jj;
    int grow = act ? (gate*HH + j) : 0;

    // register-resident half weight row (76 floats; zero-padded)
    float w[76];
    if (act){
        #pragma unroll
        for (int k=0;k<76;k++){
            int kk = half*76 + k;
            w[k] = (kk < HH) ? Whh[(long)grow*HH + kk] : 0.f;
        }
    } else {
        #pragma unroll
        for (int k=0;k<76;k++) w[k] = 0.f;
    }
    float bias = (act && half == 0) ? bhh[grow] : 0.f;

    // init h buffers
    for (int k=tid;k<152;k+=256){
        h_sm[0][k] = (k < HH) ? hinit[(long)b*hi_stride + hi_off + k] : 0.f;
        h_sm[1][k] = 0.f;
    }

    // mapped h pointers for all 4 CTAs of the cluster (incl. self)
    float* ph0 = (float*)cluster.map_shared_rank((void*)&h_sm[0][0], 0);
    float* ph1 = (float*)cluster.map_shared_rank((void*)&h_sm[0][0], 1);
    float* ph2 = (float*)cluster.map_shared_rank((void*)&h_sm[0][0], 2);
    float* ph3 = (float*)cluster.map_shared_rank((void*)&h_sm[0][0], 3);

    cluster.sync();   // init visible before any peer writes

    int p = 0;
    for (int t=0;t<T;t++){
        // prefetch gi for the combine threads (overlaps the matvec)
        float gr = 0.f, gz = 0.f, gn = 0.f;
        int jc = rank*38 + tid;
        if (tid < nj){
            const float* g = gi + ((long)b*T + t)*G3;
            gr = g[jc]; gz = g[HH + jc]; gn = g[2*HH + jc];
        }

        // split-K matvec: every thread computes a 76-element partial dot
        {
            const float4* h4 = (const float4*)&h_sm[p][half*76];
            float a0 = 0.f, a1 = 0.f, a2 = 0.f, a3 = 0.f;
            #pragma unroll
            for (int k4=0;k4<19;k4++){
                float4 hv = h4[k4];
                a0 += w[4*k4+0]*hv.x;
                a1 += w[4*k4+1]*hv.y;
                a2 += w[4*k4+2]*hv.z;
                a3 += w[4*k4+3]*hv.w;
            }
            float s = (a0 + a1) + (a2 + a3);
            s += __shfl_xor_sync(0xffffffffu, s, 1);   // pair-sum (same warp)
            if (act && half == 0) sg[gate][jj] = s + bias;
        }
        __syncthreads();

        if (tid < nj){
            float r = fast_sigmoid(gr + sg[0][tid]);
            float z = fast_sigmoid(gz + sg[1][tid]);
            float n = fast_tanh(gn + r*sg[2][tid]);
            float hp = h_sm[p][jc];
            float hn = (1.f - z)*n + z*hp;
            int dst = (1-p)*152 + jc;
            ph0[dst] = hn;                      // broadcast to all 4 CTAs (DSMEM)
            ph1[dst] = hn;
            ph2[dst] = hn;
            ph3[dst] = hn;
            out[((long)b*T + t)*HH + jc] = hn;
        }
        cluster.sync();   // all CTAs' h slices visible everywhere; orders sg reuse
        p ^= 1;
    }
}

// ---------------- fp32 tiled SGEMM (pre-charge path only; keeps charge argmax stable)
// EPI: 0=plain, 1=+bias, 2=tanh(+bias), 3=+residual
template<int TRANSB, int EPI>
__global__ void gemm_kernel(const float* __restrict__ A, const float* __restrict__ Bm,
                            const float* __restrict__ bias, const float* __restrict__ res,
                            float* __restrict__ C,
                            int M, int N, int K,
                            long sA, long sB, long sC, long sR){
    int z = blockIdx.z;
    A  += (long)z*sA;
    Bm += (long)z*sB;
    C  += (long)z*sC;
    const float* R = (EPI==3) ? (res + (long)z*sR) : res;

    int m0 = blockIdx.y*64, n0 = blockIdx.x*64;
    __shared__ float As[16][68];
    __shared__ float Bs[16][68];
    int tid = threadIdx.x;
    int tx = tid & 15, ty = tid >> 4;
    float c[4][4] = {};

    for (int kk=0; kk<K; kk+=16){
        for (int idx=tid; idx<64*16; idx+=256){
            int i = idx >> 4, k = idx & 15;
            int mi = m0 + i, ki = kk + k;
            As[k][i] = (mi < M && ki < K) ? A[(long)mi*K + ki] : 0.f;
        }
        if (TRANSB){
            for (int idx=tid; idx<64*16; idx+=256){
                int j = idx >> 4, k = idx & 15;
                int nj = n0 + j, ki = kk + k;
                Bs[k][j] = (nj < N && ki < K) ? Bm[(long)nj*K + ki] : 0.f;
            }
        } else {
            for (int idx=tid; idx<64*16; idx+=256){
                int j = idx & 63, k = idx >> 6;
                int nj = n0 + j, ki = kk + k;
                Bs[k][j] = (nj < N && ki < K) ? Bm[(long)ki*N + nj] : 0.f;
            }
        }
        __syncthreads();
        #pragma unroll
        for (int k=0;k<16;k++){
            float4 a4 = *(const float4*)&As[k][ty*4];
            float4 b4 = *(const float4*)&Bs[k][tx*4];
            float af[4] = {a4.x,a4.y,a4.z,a4.w};
            float bf[4] = {b4.x,b4.y,b4.z,b4.w};
            #pragma unroll
            for (int r=0;r<4;r++)
                #pragma unroll
                for (int cc=0;cc<4;cc++)
                    c[r][cc] += af[r]*bf[cc];
        }
        __syncthreads();
    }

    #pragma unroll
    for (int r=0;r<4;r++){
        int i = m0 + ty*4 + r;
        if (i >= M) continue;
        #pragma unroll
        for (int cc=0;cc<4;cc++){
            int j = n0 + tx*4 + cc;
            if (j >= N) continue;
            float v = c[r][cc];
            if (EPI==1 || EPI==2) v += bias[j];
            if (EPI==2) v = tanhf(v);
            if (EPI==3) v += R[(long)i*N + j];
            C[(long)i*N + j] = v;
        }
    }
}

// ---------------- tf32 tensor-core batched GEMM: 64x64 tile -------------------------
#define ST72 72
template<int TRANSB, int EPI>
__global__ void __launch_bounds__(256)
gemm_tf32_kernel(const float* __restrict__ A, const float* __restrict__ Bm,
                 const float* __restrict__ bias, const float* __restrict__ res,
                 float* __restrict__ C,
                 int M, int N, int K,
                 long sA, long sB, long sC, long sR){
    int z = blockIdx.z;
    A  += (long)z*sA;
    Bm += (long)z*sB;
    C  += (long)z*sC;
    const float* R = (EPI==3) ? (res + (long)z*sR) : res;

    __shared__ float As[16*ST72];
    __shared__ float Bs[16*ST72];
    int m0 = blockIdx.y*64, n0 = blockIdx.x*64;
    int tid = threadIdx.x;
    int lane = tid & 31, warp = tid >> 5;
    int wm = warp >> 2, wn = warp & 3;      // 2 x 4 warp grid
    int g = lane >> 2, t4 = lane & 3;

    float c[2][2][4];
    #pragma unroll
    for (int a=0;a<2;a++)
        #pragma unroll
        for (int bq=0;bq<2;bq++)
            #pragma unroll
            for (int r=0;r<4;r++) c[a][bq][r] = 0.f;

    for (int kk=0; kk<K; kk+=16){
        #pragma unroll
        for (int l=0;l<4;l++){
            int idx = tid + l*256;
            int i = idx >> 4, k = idx & 15;
            int mi = m0 + i, ki = kk + k;
            As[k*ST72 + i] = (mi < M && ki < K) ? A[(long)mi*K + ki] : 0.f;
        }
        if (TRANSB){
            #pragma unroll
            for (int l=0;l<4;l++){
                int idx = tid + l*256;
                int j = idx >> 4, k = idx & 15;
                int nj = n0 + j, ki = kk + k;
                Bs[k*ST72 + j] = (nj < N && ki < K) ? Bm[(long)nj*K + ki] : 0.f;
            }
        } else {
            #pragma unroll
            for (int l=0;l<4;l++){
                int idx = tid + l*256;
                int j = idx & 63, k = idx >> 6;
                int nj = n0 + j, ki = kk + k;
                Bs[k*ST72 + j] = (nj < N && ki < K) ? Bm[(long)ki*N + nj] : 0.f;
            }
        }
        __syncthreads();
        #pragma unroll
        for (int k8=0;k8<16;k8+=8){
            uint32_t bf[2][2];
            #pragma unroll
            for (int nt=0;nt<2;nt++){
                int nb = wn*16 + nt*8 + g;
                bf[nt][0] = f2tf32(Bs[(k8+t4)*ST72 + nb]);
                bf[nt][1] = f2tf32(Bs[(k8+t4+4)*ST72 + nb]);
            }
            #pragma unroll
            for (int mt=0;mt<2;mt++){
                int mb = wm*32 + mt*16 + g;
                uint32_t a0 = f2tf32(As[(k8+t4)*ST72 + mb]);
                uint32_t a1 = f2tf32(As[(k8+t4)*ST72 + mb + 8]);
                uint32_t a2 = f2tf32(As[(k8+t4+4)*ST72 + mb]);
                uint32_t a3 = f2tf32(As[(k8+t4+4)*ST72 + mb + 8]);
                #pragma unroll
                for (int nt=0;nt<2;nt++){
                    asm volatile(
                        "mma.sync.aligned.m16n8k8.row.col.f32.tf32.tf32.f32 "
                        "{%0,%1,%2,%3}, {%4,%5,%6,%7}, {%8,%9}, {%0,%1,%2,%3};"
                        : "+f"(c[mt][nt][0]), "+f"(c[mt][nt][1]),
                          "+f"(c[mt][nt][2]), "+f"(c[mt][nt][3])
                        : "r"(a0), "r"(a1), "r"(a2), "r"(a3),
                          "r"(bf[nt][0]), "r"(bf[nt][1]));
                }
            }
        }
        __syncthreads();
    }

    #pragma unroll
    for (int mt=0;mt<2;mt++){
        int i0 = m0 + wm*32 + mt*16 + g;
        #pragma unroll
        for (int nt=0;nt<2;nt++){
            int j0 = n0 + wn*16 + nt*8 + t4*2;
            #pragma unroll
            for (int rr=0;rr<2;rr++){
                int i = i0 + rr*8;
                if (i >= M) continue;
                #pragma unroll
                for (int cc2=0;cc2<2;cc2++){
                    int j = j0 + cc2;
                    if (j >= N) continue;
                    float v = c[mt][nt][rr*2 + cc2];
                    if (EPI==1 || EPI==2) v += bias[j];
                    if (EPI==2) v = tanhf(v);
                    if (EPI==3) v += R[(long)i*N + j];
                    C[(long)i*N + j] = v;
                }
            }
        }
    }
}

// ---------------- tf32 tensor-core GEMM for logits (128x128 tile, transposed store) ----
#define TFST 136
__global__ void __launch_bounds__(256)
logits_tf32_kernel(const float* __restrict__ A, const float* __restrict__ Bm,
                   const float* __restrict__ bias, float* __restrict__ C,
                   int M, int N, int K){
    __shared__ float As[16*TFST];
    __shared__ float Bs[16*TFST];
    int m0 = blockIdx.y*128, n0 = blockIdx.x*128;
    int tid = threadIdx.x;
    int lane = tid & 31, warp = tid >> 5;
    int wm = warp >> 2, wn = warp & 3;      // 2 x 4 warp grid
    int g = lane >> 2, t4 = lane & 3;

    float c[4][4][4];
    #pragma unroll
    for (int a=0;a<4;a++)
        #pragma unroll
        for (int bq=0;bq<4;bq++)
            #pragma unroll
            for (int r=0;r<4;r++) c[a][bq][r] = 0.f;

    for (int kk=0; kk<K; kk+=16){
        #pragma unroll
        for (int l=0;l<8;l++){
            int idx = tid + l*256;
            int i = idx >> 4, k = idx & 15;
            int ki = kk + k;
            As[k*TFST + i] = (ki < K) ? A[(long)(m0+i)*K + ki] : 0.f;  // M % 128 == 0
            int nj = n0 + i;
            Bs[k*TFST + i] = (nj < N && ki < K) ? Bm[(long)nj*K + ki] : 0.f;
        }
        __syncthreads();
        #pragma unroll
        for (int k8=0;k8<16;k8+=8){
            uint32_t bf[4][2];
            #pragma unroll
            for (int nt=0;nt<4;nt++){
                int nb = wn*32 + nt*8 + g;
                bf[nt][0] = f2tf32(Bs[(k8+t4)*TFST + nb]);
                bf[nt][1] = f2tf32(Bs[(k8+t4+4)*TFST + nb]);
            }
            #pragma unroll
            for (int mt=0;mt<4;mt++){
                int mb = wm*64 + mt*16 + g;
                uint32_t a0 = f2tf32(As[(k8+t4)*TFST + mb]);
                uint32_t a1 = f2tf32(As[(k8+t4)*TFST + mb + 8]);
                uint32_t a2 = f2tf32(As[(k8+t4+4)*TFST + mb]);
                uint32_t a3 = f2tf32(As[(k8+t4+4)*TFST + mb + 8]);
                #pragma unroll
                for (int nt=0;nt<4;nt++){
                    asm volatile(
                        "mma.sync.aligned.m16n8k8.row.col.f32.tf32.tf32.f32 "
                        "{%0,%1,%2,%3}, {%4,%5,%6,%7}, {%8,%9}, {%0,%1,%2,%3};"
                        : "+f"(c[mt][nt][0]), "+f"(c[mt][nt][1]),
                          "+f"(c[mt][nt][2]), "+f"(c[mt][nt][3])
                        : "r"(a0), "r"(a1), "r"(a2), "r"(a3),
                          "r"(bf[nt][0]), "r"(bf[nt][1]));
                }
            }
        }
        __syncthreads();
    }

    #pragma unroll
    for (int mt=0;mt<4;mt++){
        int i0 = m0 + wm*64 + mt*16 + g;
        #pragma unroll
        for (int nt=0;nt<4;nt++){
            int j0 = n0 + wn*32 + nt*8 + t4*2;
            #pragma unroll
            for (int rr=0;rr<2;rr++){
                int i = i0 + rr*8;
                int bb2 = i / TT, tt2 = i % TT;
                long rowoff = ((long)(tt2*BB + bb2))*N;
                #pragma unroll
                for (int cc2=0;cc2<2;cc2++){
                    int j = j0 + cc2;
                    if (j < N)
                        C[rowoff + j] = c[mt][nt][rr*2 + cc2] + bias[j];
                }
            }
        }
    }
}

// ---------------- softmaxes ----------------
__global__ void mask_softmax128(float* __restrict__ att){
    long row = blockIdx.x;
    int tid = threadIdx.x;  // 128 threads
    __shared__ float red[4];
    float x = att[row*LL + tid];
    float xm = (x == 0.f) ? -INFINITY : x;
    float M = block_max<4>(xm, red);
    float e = isinf(M) ? 0.f : expf(xm - M);
    float S = block_sum<4>(e, red);
    att[row*LL + tid] = (S > 0.f) ? e / S : 0.f;
}

__global__ void softmax512(float* __restrict__ x){
    long row = blockIdx.x;
    int tid = threadIdx.x;
    __shared__ float red[8];
    float* p = x + row*(long)LS;
    float v0 = p[tid], v1 = p[tid + 256];
    float M = block_max<8>(fmaxf(v0, v1), red);
    float e0 = expf(v0 - M), e1 = expf(v1 - M);
    float S = block_sum<8>(e0 + e1, red);
    float inv = 1.f / S;
    p[tid] = e0*inv; p[tid + 256] = e1*inv;
}

__global__ void concat_kernel(const float* __restrict__ dec_out, const float* __restrict__ ctx,
                              float* __restrict__ cat){
    long id = (long)blockIdx.x*blockDim.x + threadIdx.x;
    long n = (long)BB*TT*2*HH;
    if (id < n){
        long m = id / (2*HH); int j = (int)(id % (2*HH));
        cat[id] = (j < HH) ? dec_out[m*HH + j] : ctx[m*HH + (j - HH)];
    }
}

__global__ void nll_kernel(const float* __restrict__ logits_out, const int* __restrict__ tgts,
                           float* __restrict__ nll, float* __restrict__ validf){
    int row = blockIdx.x;           // b*TT + t
    int tid = threadIdx.x;          // 256 threads
    int b = row / TT, t = row % TT;
    const float* x = logits_out + ((long)(t*BB + b))*VV;
    __shared__ float red[8];
    float m = -INFINITY;
    for (int i=tid;i<VV;i+=256) m = fmaxf(m, x[i]);
    float M = block_max<8>(m, red);
    float s = 0.f;
    for (int i=tid;i<VV;i+=256) s += expf(x[i] - M);
    float S = block_sum<8>(s, red);
    if (tid == 0){
        int tg = tgts[row];
        float v = (tg != EOS_TOK) ? 1.f : 0.f;
        nll[row] = v * ((M + logf(S)) - x[tg]);
        validf[row] = v;
    }
}

__global__ void loss_reduce_kernel(const float* __restrict__ nll, const float* __restrict__ val,
                                   float* __restrict__ out_loss){
    __shared__ float red[8];
    int t = threadIdx.x;  // 256 threads
    float v = 0.f;
    if (t < TT){
        float s = 0.f, c = 0.f;
        for (int b=0;b<BB;b++){ s += nll[b*TT + t]; c += val[b*TT + t]; }
        v = s / fmaxf(c, 1.f);
    }
    float tot = block_sum<8>(v, red);
    if (t == 0) out_loss[0] = tot;
}

// ---------------- host side ----------------
static void launch_gemm_f32(int transb, int epi,
                            const float* A, const float* Bm, const float* bias, const float* res,
                            float* C, int M, int N, int K,
                            long sA, long sB, long sC, long sR, int batch){
    dim3 gr((N + 63)/64, (M + 63)/64, batch);
    dim3 bl(256);
    if (transb){
        if (epi == 0)      gemm_kernel<1,0><<<gr,bl>>>(A,Bm,bias,res,C,M,N,K,sA,sB,sC,sR);
        else if (epi == 1) gemm_kernel<1,1><<<gr,bl>>>(A,Bm,bias,res,C,M,N,K,sA,sB,sC,sR);
        else               gemm_kernel<1,2><<<gr,bl>>>(A,Bm,bias,res,C,M,N,K,sA,sB,sC,sR);
    } else {
        if (epi == 0)      gemm_kernel<0,0><<<gr,bl>>>(A,Bm,bias,res,C,M,N,K,sA,sB,sC,sR);
        else               gemm_kernel<0,3><<<gr,bl>>>(A,Bm,bias,res,C,M,N,K,sA,sB,sC,sR);
    }
}

static void launch_gemm_tf32(int transb, int epi,
                             const float* A, const float* Bm, const float* bias, const float* res,
                             float* C, int M, int N, int K,
                             long sA, long sB, long sC, long sR, int batch){
    dim3 gr((N + 63)/64, (M + 63)/64, batch);
    dim3 bl(256);
    if (transb){
        if (epi == 0)      gemm_tf32_kernel<1,0><<<gr,bl>>>(A,Bm,bias,res,C,M,N,K,sA,sB,sC,sR);
        else if (epi == 1) gemm_tf32_kernel<1,1><<<gr,bl>>>(A,Bm,bias,res,C,M,N,K,sA,sB,sC,sR);
        else               gemm_tf32_kernel<1,2><<<gr,bl>>>(A,Bm,bias,res,C,M,N,K,sA,sB,sC,sR);
    } else {
        if (epi == 0)      gemm_tf32_kernel<0,0><<<gr,bl>>>(A,Bm,bias,res,C,M,N,K,sA,sB,sC,sR);
        else               gemm_tf32_kernel<0,3><<<gr,bl>>>(A,Bm,bias,res,C,M,N,K,sA,sB,sC,sR);
    }
}

template<typename T> static T* sym(const void* s){
    void* p = nullptr;
    cudaGetSymbolAddress(&p, s);
    return (T*)p;
}

extern "C" void kernel_launch(void* const* d_in, const int* in_sizes, int n_in,
                              void* d_out, int out_size){
    const int*   srcs        = (const int*)  d_in[0];
    const int*   tgts        = (const int*)  d_in[1];
    const int*   law_tokens  = (const int*)  d_in[2];
    const float* src_embed   = (const float*)d_in[3];
    const float* enc_rnn_Wih = (const float*)d_in[4];
    const float* enc_rnn_Whh = (const float*)d_in[5];
    const float* enc_rnn_bih = (const float*)d_in[6];
    const float* enc_rnn_bhh = (const float*)d_in[7];
    const float* enc_gru_Wih = (const float*)d_in[8];
    const float* enc_gru_Whh = (const float*)d_in[9];
    const float* enc_gru_bih = (const float*)d_in[10];
    const float* enc_gru_bhh = (const float*)d_in[11];
    const float* dec_embed   = (const float*)d_in[12];
    const float* dec_rnn_Wih = (const float*)d_in[13];
    const float* dec_rnn_Whh = (const float*)d_in[14];
    const float* dec_rnn_bih = (const float*)d_in[15];
    const float* dec_rnn_bhh = (const float*)d_in[16];
    const float* Ww          = (const float*)d_in[17];
    const float* bw          = (const float*)d_in[18];
    const float* Wp          = (const float*)d_in[19];
    const float* bp          = (const float*)d_in[20];
    const float* Wc          = (const float*)d_in[21];
    const float* bc          = (const float*)d_in[22];
    float* out = (float*)d_out;

    float* h0       = sym<float>(g_h0);
    float* emb_src  = sym<float>(g_emb_src);
    float* gi       = sym<float>(g_gi);
    float* enc1     = sym<float>(g_enc_outs1);
    float* chh      = sym<float>(g_chh);
    int*   leg_toks = sym<int>(g_legal_toks);
    float* emb_leg  = sym<float>(g_emb_leg);
    float* gi_leg   = sym<float>(g_gi_leg);
    float* legals   = sym<float>(g_legals);
    float* att      = sym<float>(g_att);
    float* ca       = sym<float>(g_ca);
    float* enc2     = sym<float>(g_enc_outs);
    int*   dec_in   = sym<int>(g_dec_in);
    float* emb_dec  = sym<float>(g_emb_dec);
    float* gi_dec   = sym<float>(g_gi_dec);
    float* dec_outb = sym<float>(g_dec_out);
    float* scores   = sym<float>(g_scores);
    float* ctx      = sym<float>(g_ctx);
    float* cat      = sym<float>(g_concat);
    float* co       = sym<float>(g_co);
    float* nll      = sym<float>(g_nll);
    float* valf     = sym<float>(g_val);

    // h0 = zeros
    zero_kernel<<<(BB*HH + 255)/256, 256>>>(h0, BB*HH);

    // ---- encoder pass 1 (fp32: feeds charge argmax) ----
    {
        long n = (long)BB*LS*EE;
        gather_kernel<<<(unsigned)((n + 255)/256), 256>>>(emb_src, src_embed, srcs, (long)BB*LS, EE);
    }
    launch_gemm_f32(1, 1, emb_src, enc_rnn_Wih, enc_rnn_bih, nullptr, gi,
                    BB*LS, G3, EE, 0, 0, 0, 0, 1);
    gru_seq_kernel<<<4*BB, 256>>>(gi, LS, enc_rnn_Whh, enc_rnn_bhh, h0, HH, 0, enc1);

    // ---- charge prediction + legal tokens (fp32) ----
    mean_kernel<<<BB, 160>>>(enc1, chh);
    charge_kernel<<<BB, 128>>>(chh, Wc, bc, law_tokens, out + OUT_CHARGE, leg_toks);

    // ---- legal encoding (post-argmax: tf32) ----
    {
        long n = (long)BB*LL*EE;
        gather_kernel<<<(unsigned)((n + 255)/256), 256>>>(emb_leg, src_embed, leg_toks, (long)BB*LL, EE);
    }
    launch_gemm_tf32(1, 1, emb_leg, enc_rnn_Wih, enc_rnn_bih, nullptr, gi_leg,
                     BB*LL, G3, EE, 0, 0, 0, 0, 1);
    gru_seq_kernel<<<4*BB, 256>>>(gi_leg, LL, enc_rnn_Whh, enc_rnn_bhh, h0, HH, 0, legals);

    // ---- mask attention (tf32) ----
    launch_gemm_tf32(1, 0, enc1, legals, nullptr, nullptr, att,
                     LS, LL, HH, (long)LS*HH, (long)LL*HH, (long)LS*LL, 0, BB);
    mask_softmax128<<<BB*LS, 128>>>(att);
    launch_gemm_tf32(0, 3, att, legals, nullptr, enc1, ca,
                     LS, HH, LL, (long)LS*LL, (long)LL*HH, (long)LS*HH, (long)LS*HH, BB);

    // ---- encoder pass 2 (tf32 gi) ----
    launch_gemm_tf32(1, 1, ca, enc_gru_Wih, enc_gru_bih, nullptr, gi,
                     BB*LS, G3, HH, 0, 0, 0, 0, 1);
    gru_seq_kernel<<<4*BB, 256>>>(gi, LS, enc_gru_Whh, enc_gru_bhh, h0, HH, 0, enc2);

    // ---- decoder GRU (teacher forcing, tf32 gi), h0 = enc2[:,511,:] ----
    dec_tokens_kernel<<<(BB*TT + 255)/256, 256>>>(tgts, dec_in);
    {
        long n = (long)BB*TT*EE;
        gather_kernel<<<(unsigned)((n + 255)/256), 256>>>(emb_dec, dec_embed, dec_in, (long)BB*TT, EE);
    }
    launch_gemm_tf32(1, 1, emb_dec, dec_rnn_Wih, dec_rnn_bih, nullptr, gi_dec,
                     BB*TT, G3, EE, 0, 0, 0, 0, 1);
    gru_seq_kernel<<<4*BB, 256>>>(gi_dec, TT, dec_rnn_Whh, dec_rnn_bhh,
                                  enc2, (long)LS*HH, (long)(LS-1)*HH, dec_outb);

    // ---- decoder attention (tf32) ----
    launch_gemm_tf32(1, 0, dec_outb, enc2, nullptr, nullptr, scores,
                     TT, LS, HH, (long)TT*HH, (long)LS*HH, (long)TT*LS, 0, BB);
    softmax512<<<BB*TT, 256>>>(scores);
    launch_gemm_tf32(0, 0, scores, enc2, nullptr, nullptr, ctx,
                     TT, HH, LS, (long)TT*LS, (long)LS*HH, (long)TT*HH, 0, BB);

    // ---- co = tanh([dec_out|ctx] @ Ww^T + bw) (tf32) ----
    {
        long n = (long)BB*TT*2*HH;
        concat_kernel<<<(unsigned)((n + 255)/256), 256>>>(dec_outb, ctx, cat);
    }
    launch_gemm_tf32(1, 2, cat, Ww, bw, nullptr, co,
                     BB*TT, HH, 2*HH, 0, 0, 0, 0, 1);

    // ---- logits = co @ Wp^T + bp (tf32 tensor cores), stored transposed into d_out ----
    {
        dim3 gr((VV + 127)/128, (BB*TT)/128, 1);
        logits_tf32_kernel<<<gr, 256>>>(co, Wp, bp, out, BB*TT, VV, HH);
    }

    // ---- loss ----
    nll_kernel<<<BB*TT, 256>>>(out, tgts, nll, valf);
    loss_reduce_kernel<<<1, 256>>>(nll, valf, out + OUT_LOSS);
}

// round 17
// speedup vs baseline: 1.8458x; 1.0052x over previous
#include <cuda_runtime.h>
#include <cooperative_groups.h>
#include <math.h>

namespace cg = cooperative_groups;

// ---------------- problem constants ----------------
#define BB   64      // batch
#define LS   512     // source length
#define LL   128     // law/legal length
#define TT   150     // target length
#define HH   150     // hidden
#define EE   200     // embed
#define G3   450     // 3*HH
#define VV   10000   // target vocab
#define NCH  62      // charges
#define SOS_TOK 2
#define EOS_TOK 1

#define OUT_LOSS   96000000L   // TT*BB*VV
#define OUT_CHARGE 96000001L

// ---------------- scratch (device globals; no allocation allowed) ----------------
__device__ float g_h0[BB*HH];
__device__ float g_emb_src[BB*LS*EE];
__device__ float g_gi[BB*LS*G3];
__device__ float g_enc_outs1[BB*LS*HH];
__device__ float g_chh[BB*HH];
__device__ int   g_legal_toks[BB*LL];
__device__ float g_emb_leg[BB*LL*EE];
__device__ float g_gi_leg[BB*LL*G3];
__device__ float g_legals[BB*LL*HH];
__device__ float g_att[BB*LS*LL];
__device__ float g_ca[BB*LS*HH];
__device__ float g_enc_outs[BB*LS*HH];
__device__ int   g_dec_in[BB*TT];
__device__ float g_emb_dec[BB*TT*EE];
__device__ float g_gi_dec[BB*TT*G3];
__device__ float g_dec_out[BB*TT*HH];
__device__ float g_scores[BB*TT*LS];
__device__ float g_ctx[BB*TT*HH];
__device__ float g_concat[BB*TT*2*HH];
__device__ float g_co[BB*TT*HH];
__device__ float g_nll[BB*TT];
__device__ float g_val[BB*TT];

// ---------------- small helpers ----------------
__device__ __forceinline__ float warp_max(float v){
    #pragma unroll
    for (int o=16;o;o>>=1) v = fmaxf(v, __shfl_xor_sync(0xffffffffu, v, o));
    return v;
}
__device__ __forceinline__ float warp_sum(float v){
    #pragma unroll
    for (int o=16;o;o>>=1) v += __shfl_xor_sync(0xffffffffu, v, o);
    return v;
}
template<int NW>
__device__ __forceinline__ float block_max(float v, float* red){
    v = warp_max(v);
    int w = threadIdx.x >> 5;
    if ((threadIdx.x & 31) == 0) red[w] = v;
    __syncthreads();
    float r = red[0];
    #pragma unroll
    for (int i=1;i<NW;i++) r = fmaxf(r, red[i]);
    __syncthreads();
    return r;
}
template<int NW>
__device__ __forceinline__ float block_sum(float v, float* red){
    v = warp_sum(v);
    int w = threadIdx.x >> 5;
    if ((threadIdx.x & 31) == 0) red[w] = v;
    __syncthreads();
    float r = red[0];
    #pragma unroll
    for (int i=1;i<NW;i++) r += red[i];
    __syncthreads();
    return r;
}

__device__ __forceinline__ uint32_t f2tf32(float f){
    uint32_t u;
    asm("cvt.rna.tf32.f32 %0, %1;" : "=r"(u) : "f"(f));
    return u;
}

// fast sigmoid / tanh via MUFU (__expf rel err ~1e-7; clamped against overflow)
__device__ __forceinline__ float fast_sigmoid(float x){
    x = fminf(fmaxf(x, -30.f), 30.f);
    return __fdividef(1.f, 1.f + __expf(-x));
}
__device__ __forceinline__ float fast_tanh(float x){
    x = fminf(fmaxf(x, -15.f), 15.f);
    float e = __expf(2.f*x);
    return __fdividef(e - 1.f, e + 1.f);
}

// ---------------- trivial kernels ----------------
__global__ void zero_kernel(float* p, long n){
    long i = (long)blockIdx.x*blockDim.x + threadIdx.x;
    if (i < n) p[i] = 0.f;
}

__global__ void gather_kernel(float* __restrict__ out, const float* __restrict__ table,
                              const int* __restrict__ toks, long nrows, int E){
    long id = (long)blockIdx.x*blockDim.x + threadIdx.x;
    if (id < nrows*(long)E){
        long r = id / E; int j = (int)(id % E);
        out[id] = table[(long)toks[r]*E + j];
    }
}

__global__ void dec_tokens_kernel(const int* __restrict__ tgts, int* __restrict__ dec_in){
    int id = blockIdx.x*blockDim.x + threadIdx.x;
    if (id < BB*TT){
        int b = id / TT, t = id % TT;
        dec_in[id] = (t == 0) ? SOS_TOK : tgts[b*TT + t - 1];
    }
}

__global__ void mean_kernel(const float* __restrict__ outs1, float* __restrict__ chh){
    int b = blockIdx.x; int j = threadIdx.x;
    if (j < HH){
        float s = 0.f;
        for (int t=0;t<LS;t++) s += outs1[((long)b*LS + t)*HH + j];
        chh[b*HH + j] = s * (1.f/LS);
    }
}

__global__ void charge_kernel(const float* __restrict__ chh, const float* __restrict__ Wc,
                              const float* __restrict__ bc, const int* __restrict__ law_tokens,
                              float* __restrict__ out_charge, int* __restrict__ legal_toks){
    int b = blockIdx.x; int tid = threadIdx.x;   // 128 threads
    __shared__ float h[HH];
    __shared__ float sc[NCH];
    __shared__ int cid;
    for (int i=tid;i<HH;i+=128) h[i] = chh[b*HH + i];
    __syncthreads();
    if (tid < NCH){
        float a = bc[tid];
        const float* w = Wc + tid*HH;
        for (int k=0;k<HH;k++) a += h[k]*w[k];
        sc[tid] = a;
        out_charge[b*NCH + tid] = a;
    }
    __syncthreads();
    if (tid == 0){
        int best = 0; float bv = sc[0];
        for (int c=1;c<NCH;c++) if (sc[c] > bv){ bv = sc[c]; best = c; }
        cid = best;
    }
    __syncthreads();
    for (int i=tid;i<LL;i+=128) legal_toks[b*LL + i] = law_tokens[cid*LL + i];
}

// ---------------- persistent GRU sequence kernel (R16 config — frozen) --------------
__global__ void __cluster_dims__(4,1,1) __launch_bounds__(256,2)
gru_seq_kernel(const float* __restrict__ gi, int T,
               const float* __restrict__ Whh, const float* __restrict__ bhh,
               const float* __restrict__ hinit, long hi_stride, long hi_off,
               float* __restrict__ out)
{
    cg::cluster_group cluster = cg::this_cluster();
    int rank = cluster.block_rank();            // 0..3
    int b = blockIdx.x >> 2;                    // batch row
    int tid = threadIdx.x;

    __shared__ float h_sm[2][152];   // full h, padded for float4
    __shared__ float sg[3][40];      // this CTA's gate partials

    int nj = (rank < 3) ? 38 : 36;   // 150 = 38+38+38+36

    // matvec mapping: 2 threads per gate row; pairs (2r, 2r+1) share a warp
    int row = tid >> 1;              // 0..127
    int half = tid & 1;              // K-half: [0,76) or [76,152)
    int gate = row / 38;             // 0..2 valid; 3 = padding rows
    int jj = row - gate*38;
    bool act = (gate < 3) && (jj < nj);
    int j = rank*38 + jj;
    int grow = act ? (gate*HH + j) : 0;

    // register-resident half weight row (76 floats; zero-padded)
    float w[76];
    if (act){
        #pragma unroll
        for (int k=0;k<76;k++){
            int kk = half*76 + k;
            w[k] = (kk < HH) ? Whh[(long)grow*HH + kk] : 0.f;
        }
    } else {
        #pragma unroll
        for (int k=0;k<76;k++) w[k] = 0.f;
    }
    float bias = (act && half == 0) ? bhh[grow] : 0.f;

    // init h buffers
    for (int k=tid;k<152;k+=256){
        h_sm[0][k] = (k < HH) ? hinit[(long)b*hi_stride + hi_off + k] : 0.f;
        h_sm[1][k] = 0.f;
    }

    // mapped h pointers for all 4 CTAs of the cluster (incl. self)
    float* ph0 = (float*)cluster.map_shared_rank((void*)&h_sm[0][0], 0);
    float* ph1 = (float*)cluster.map_shared_rank((void*)&h_sm[0][0], 1);
    float* ph2 = (float*)cluster.map_shared_rank((void*)&h_sm[0][0], 2);
    float* ph3 = (float*)cluster.map_shared_rank((void*)&h_sm[0][0], 3);

    cluster.sync();   // init visible before any peer writes

    int p = 0;
    for (int t=0;t<T;t++){
        // prefetch gi for the combine threads (overlaps the matvec)
        float gr = 0.f, gz = 0.f, gn = 0.f;
        int jc = rank*38 + tid;
        if (tid < nj){
            const float* g = gi + ((long)b*T + t)*G3;
            gr = g[jc]; gz = g[HH + jc]; gn = g[2*HH + jc];
        }

        // split-K matvec: every thread computes a 76-element partial dot
        {
            const float4* h4 = (const float4*)&h_sm[p][half*76];
            float a0 = 0.f, a1 = 0.f, a2 = 0.f, a3 = 0.f;
            #pragma unroll
            for (int k4=0;k4<19;k4++){
                float4 hv = h4[k4];
                a0 += w[4*k4+0]*hv.x;
                a1 += w[4*k4+1]*hv.y;
                a2 += w[4*k4+2]*hv.z;
                a3 += w[4*k4+3]*hv.w;
            }
            float s = (a0 + a1) + (a2 + a3);
            s += __shfl_xor_sync(0xffffffffu, s, 1);   // pair-sum (same warp)
            if (act && half == 0) sg[gate][jj] = s + bias;
        }
        __syncthreads();

        if (tid < nj){
            float r = fast_sigmoid(gr + sg[0][tid]);
            float z = fast_sigmoid(gz + sg[1][tid]);
            float n = fast_tanh(gn + r*sg[2][tid]);
            float hp = h_sm[p][jc];
            float hn = (1.f - z)*n + z*hp;
            int dst = (1-p)*152 + jc;
            ph0[dst] = hn;                      // broadcast to all 4 CTAs (DSMEM)
            ph1[dst] = hn;
            ph2[dst] = hn;
            ph3[dst] = hn;
            out[((long)b*T + t)*HH + jc] = hn;
        }
        cluster.sync();   // all CTAs' h slices visible everywhere; orders sg reuse
        p ^= 1;
    }
}

// ---------------- fp32 tiled SGEMM (pre-charge path only; keeps charge argmax stable)
template<int TRANSB, int EPI>
__global__ void gemm_kernel(const float* __restrict__ A, const float* __restrict__ Bm,
                            const float* __restrict__ bias, const float* __restrict__ res,
                            float* __restrict__ C,
                            int M, int N, int K,
                            long sA, long sB, long sC, long sR){
    int z = blockIdx.z;
    A  += (long)z*sA;
    Bm += (long)z*sB;
    C  += (long)z*sC;
    const float* R = (EPI==3) ? (res + (long)z*sR) : res;

    int m0 = blockIdx.y*64, n0 = blockIdx.x*64;
    __shared__ float As[16][68];
    __shared__ float Bs[16][68];
    int tid = threadIdx.x;
    int tx = tid & 15, ty = tid >> 4;
    float c[4][4] = {};

    for (int kk=0; kk<K; kk+=16){
        for (int idx=tid; idx<64*16; idx+=256){
            int i = idx >> 4, k = idx & 15;
            int mi = m0 + i, ki = kk + k;
            As[k][i] = (mi < M && ki < K) ? A[(long)mi*K + ki] : 0.f;
        }
        if (TRANSB){
            for (int idx=tid; idx<64*16; idx+=256){
                int j = idx >> 4, k = idx & 15;
                int nj = n0 + j, ki = kk + k;
                Bs[k][j] = (nj < N && ki < K) ? Bm[(long)nj*K + ki] : 0.f;
            }
        } else {
            for (int idx=tid; idx<64*16; idx+=256){
                int j = idx & 63, k = idx >> 6;
                int nj = n0 + j, ki = kk + k;
                Bs[k][j] = (nj < N && ki < K) ? Bm[(long)ki*N + nj] : 0.f;
            }
        }
        __syncthreads();
        #pragma unroll
        for (int k=0;k<16;k++){
            float4 a4 = *(const float4*)&As[k][ty*4];
            float4 b4 = *(const float4*)&Bs[k][tx*4];
            float af[4] = {a4.x,a4.y,a4.z,a4.w};
            float bf[4] = {b4.x,b4.y,b4.z,b4.w};
            #pragma unroll
            for (int r=0;r<4;r++)
                #pragma unroll
                for (int cc=0;cc<4;cc++)
                    c[r][cc] += af[r]*bf[cc];
        }
        __syncthreads();
    }

    #pragma unroll
    for (int r=0;r<4;r++){
        int i = m0 + ty*4 + r;
        if (i >= M) continue;
        #pragma unroll
        for (int cc=0;cc<4;cc++){
            int j = n0 + tx*4 + cc;
            if (j >= N) continue;
            float v = c[r][cc];
            if (EPI==1 || EPI==2) v += bias[j];
            if (EPI==2) v = tanhf(v);
            if (EPI==3) v += R[(long)i*N + j];
            C[(long)i*N + j] = v;
        }
    }
}

// ---------------- tf32 tensor-core batched GEMM: 64x64 tile -------------------------
#define ST72 72
template<int TRANSB, int EPI>
__global__ void __launch_bounds__(256)
gemm_tf32_kernel(const float* __restrict__ A, const float* __restrict__ Bm,
                 const float* __restrict__ bias, const float* __restrict__ res,
                 float* __restrict__ C,
                 int M, int N, int K,
                 long sA, long sB, long sC, long sR){
    int z = blockIdx.z;
    A  += (long)z*sA;
    Bm += (long)z*sB;
    C  += (long)z*sC;
    const float* R = (EPI==3) ? (res + (long)z*sR) : res;

    __shared__ float As[16*ST72];
    __shared__ float Bs[16*ST72];
    int m0 = blockIdx.y*64, n0 = blockIdx.x*64;
    int tid = threadIdx.x;
    int lane = tid & 31, warp = tid >> 5;
    int wm = warp >> 2, wn = warp & 3;      // 2 x 4 warp grid
    int g = lane >> 2, t4 = lane & 3;

    float c[2][2][4];
    #pragma unroll
    for (int a=0;a<2;a++)
        #pragma unroll
        for (int bq=0;bq<2;bq++)
            #pragma unroll
            for (int r=0;r<4;r++) c[a][bq][r] = 0.f;

    for (int kk=0; kk<K; kk+=16){
        #pragma unroll
        for (int l=0;l<4;l++){
            int idx = tid + l*256;
            int i = idx >> 4, k = idx & 15;
            int mi = m0 + i, ki = kk + k;
            As[k*ST72 + i] = (mi < M && ki < K) ? A[(long)mi*K + ki] : 0.f;
        }
        if (TRANSB){
            #pragma unroll
            for (int l=0;l<4;l++){
                int idx = tid + l*256;
                int j = idx >> 4, k = idx & 15;
                int nj = n0 + j, ki = kk + k;
                Bs[k*ST72 + j] = (nj < N && ki < K) ? Bm[(long)nj*K + ki] : 0.f;
            }
        } else {
            #pragma unroll
            for (int l=0;l<4;l++){
                int idx = tid + l*256;
                int j = idx & 63, k = idx >> 6;
                int nj = n0 + j, ki = kk + k;
                Bs[k*ST72 + j] = (nj < N && ki < K) ? Bm[(long)ki*N + nj] : 0.f;
            }
        }
        __syncthreads();
        #pragma unroll
        for (int k8=0;k8<16;k8+=8){
            uint32_t bf[2][2];
            #pragma unroll
            for (int nt=0;nt<2;nt++){
                int nb = wn*16 + nt*8 + g;
                bf[nt][0] = f2tf32(Bs[(k8+t4)*ST72 + nb]);
                bf[nt][1] = f2tf32(Bs[(k8+t4+4)*ST72 + nb]);
            }
            #pragma unroll
            for (int mt=0;mt<2;mt++){
                int mb = wm*32 + mt*16 + g;
                uint32_t a0 = f2tf32(As[(k8+t4)*ST72 + mb]);
                uint32_t a1 = f2tf32(As[(k8+t4)*ST72 + mb + 8]);
                uint32_t a2 = f2tf32(As[(k8+t4+4)*ST72 + mb]);
                uint32_t a3 = f2tf32(As[(k8+t4+4)*ST72 + mb + 8]);
                #pragma unroll
                for (int nt=0;nt<2;nt++){
                    asm volatile(
                        "mma.sync.aligned.m16n8k8.row.col.f32.tf32.tf32.f32 "
                        "{%0,%1,%2,%3}, {%4,%5,%6,%7}, {%8,%9}, {%0,%1,%2,%3};"
                        : "+f"(c[mt][nt][0]), "+f"(c[mt][nt][1]),
                          "+f"(c[mt][nt][2]), "+f"(c[mt][nt][3])
                        : "r"(a0), "r"(a1), "r"(a2), "r"(a3),
                          "r"(bf[nt][0]), "r"(bf[nt][1]));
                }
            }
        }
        __syncthreads();
    }

    #pragma unroll
    for (int mt=0;mt<2;mt++){
        int i0 = m0 + wm*32 + mt*16 + g;
        #pragma unroll
        for (int nt=0;nt<2;nt++){
            int j0 = n0 + wn*16 + nt*8 + t4*2;
            #pragma unroll
            for (int rr=0;rr<2;rr++){
                int i = i0 + rr*8;
                if (i >= M) continue;
                #pragma unroll
                for (int cc2=0;cc2<2;cc2++){
                    int j = j0 + cc2;
                    if (j >= N) continue;
                    float v = c[mt][nt][rr*2 + cc2];
                    if (EPI==1 || EPI==2) v += bias[j];
                    if (EPI==2) v = tanhf(v);
                    if (EPI==3) v += R[(long)i*N + j];
                    C[(long)i*N + j] = v;
                }
            }
        }
    }
}

// ---------------- tf32 tensor-core GEMM for logits (128x128 tile, transposed store) ----
#define TFST 136
__global__ void __launch_bounds__(256)
logits_tf32_kernel(const float* __restrict__ A, const float* __restrict__ Bm,
                   const float* __restrict__ bias, float* __restrict__ C,
                   int M, int N, int K){
    __shared__ float As[16*TFST];
    __shared__ float Bs[16*TFST];
    int m0 = blockIdx.y*128, n0 = blockIdx.x*128;
    int tid = threadIdx.x;
    int lane = tid & 31, warp = tid >> 5;
    int wm = warp >> 2, wn = warp & 3;      // 2 x 4 warp grid
    int g = lane >> 2, t4 = lane & 3;

    float c[4][4][4];
    #pragma unroll
    for (int a=0;a<4;a++)
        #pragma unroll
        for (int bq=0;bq<4;bq++)
            #pragma unroll
            for (int r=0;r<4;r++) c[a][bq][r] = 0.f;

    for (int kk=0; kk<K; kk+=16){
        #pragma unroll
        for (int l=0;l<8;l++){
            int idx = tid + l*256;
            int i = idx >> 4, k = idx & 15;
            int ki = kk + k;
            As[k*TFST + i] = (ki < K) ? A[(long)(m0+i)*K + ki] : 0.f;  // M % 128 == 0
            int nj = n0 + i;
            Bs[k*TFST + i] = (nj < N && ki < K) ? Bm[(long)nj*K + ki] : 0.f;
        }
        __syncthreads();
        #pragma unroll
        for (int k8=0;k8<16;k8+=8){
            uint32_t bf[4][2];
            #pragma unroll
            for (int nt=0;nt<4;nt++){
                int nb = wn*32 + nt*8 + g;
                bf[nt][0] = f2tf32(Bs[(k8+t4)*TFST + nb]);
                bf[nt][1] = f2tf32(Bs[(k8+t4+4)*TFST + nb]);
            }
            #pragma unroll
            for (int mt=0;mt<4;mt++){
                int mb = wm*64 + mt*16 + g;
                uint32_t a0 = f2tf32(As[(k8+t4)*TFST + mb]);
                uint32_t a1 = f2tf32(As[(k8+t4)*TFST + mb + 8]);
                uint32_t a2 = f2tf32(As[(k8+t4+4)*TFST + mb]);
                uint32_t a3 = f2tf32(As[(k8+t4+4)*TFST + mb + 8]);
                #pragma unroll
                for (int nt=0;nt<4;nt++){
                    asm volatile(
                        "mma.sync.aligned.m16n8k8.row.col.f32.tf32.tf32.f32 "
                        "{%0,%1,%2,%3}, {%4,%5,%6,%7}, {%8,%9}, {%0,%1,%2,%3};"
                        : "+f"(c[mt][nt][0]), "+f"(c[mt][nt][1]),
                          "+f"(c[mt][nt][2]), "+f"(c[mt][nt][3])
                        : "r"(a0), "r"(a1), "r"(a2), "r"(a3),
                          "r"(bf[nt][0]), "r"(bf[nt][1]));
                }
            }
        }
        __syncthreads();
    }

    #pragma unroll
    for (int mt=0;mt<4;mt++){
        int i0 = m0 + wm*64 + mt*16 + g;
        #pragma unroll
        for (int nt=0;nt<4;nt++){
            int j0 = n0 + wn*32 + nt*8 + t4*2;
            #pragma unroll
            for (int rr=0;rr<2;rr++){
                int i = i0 + rr*8;
                int bb2 = i / TT, tt2 = i % TT;
                long rowoff = ((long)(tt2*BB + bb2))*N;
                #pragma unroll
                for (int cc2=0;cc2<2;cc2++){
                    int j = j0 + cc2;
                    if (j < N)
                        C[rowoff + j] = c[mt][nt][rr*2 + cc2] + bias[j];
                }
            }
        }
    }
}

// ---------------- softmaxes (MUFU __expf — rel err ~1e-7, safe under 5e-4 budget) ----
__global__ void mask_softmax128(float* __restrict__ att){
    long row = blockIdx.x;
    int tid = threadIdx.x;  // 128 threads
    __shared__ float red[4];
    float x = att[row*LL + tid];
    float xm = (x == 0.f) ? -INFINITY : x;
    float M = block_max<4>(xm, red);
    float e = isinf(M) ? 0.f : __expf(xm - M);
    float S = block_sum<4>(e, red);
    att[row*LL + tid] = (S > 0.f) ? __fdividef(e, S) : 0.f;
}

__global__ void softmax512(float* __restrict__ x){
    long row = blockIdx.x;
    int tid = threadIdx.x;
    __shared__ float red[8];
    float* p = x + row*(long)LS;
    float v0 = p[tid], v1 = p[tid + 256];
    float M = block_max<8>(fmaxf(v0, v1), red);
    float e0 = __expf(v0 - M), e1 = __expf(v1 - M);
    float S = block_sum<8>(e0 + e1, red);
    float inv = __fdividef(1.f, S);
    p[tid] = e0*inv; p[tid + 256] = e1*inv;
}

__global__ void concat_kernel(const float* __restrict__ dec_out, const float* __restrict__ ctx,
                              float* __restrict__ cat){
    long id = (long)blockIdx.x*blockDim.x + threadIdx.x;
    long n = (long)BB*TT*2*HH;
    if (id < n){
        long m = id / (2*HH); int j = (int)(id % (2*HH));
        cat[id] = (j < HH) ? dec_out[m*HH + j] : ctx[m*HH + (j - HH)];
    }
}

// per-(b,t) NLL: float4-vectorized scans + MUFU __expf/__logf.
// 96M libm expf was costing ~0.5ms chip-wide; __expf is ~3 instr vs ~18.
__global__ void nll_kernel(const float* __restrict__ logits_out, const int* __restrict__ tgts,
                           float* __restrict__ nll, float* __restrict__ validf){
    int row = blockIdx.x;           // b*TT + t
    int tid = threadIdx.x;          // 256 threads
    int b = row / TT, t = row % TT;
    const float* x = logits_out + ((long)(t*BB + b))*VV;
    const float4* x4 = (const float4*)x;      // VV % 4 == 0, d_out is 16B-aligned
    const int NV4 = VV/4;                     // 2500
    __shared__ float red[8];

    float m = -INFINITY;
    for (int i=tid;i<NV4;i+=256){
        float4 v = x4[i];
        m = fmaxf(m, fmaxf(fmaxf(v.x, v.y), fmaxf(v.z, v.w)));
    }
    float M = block_max<8>(m, red);

    float s = 0.f;
    for (int i=tid;i<NV4;i+=256){
        float4 v = x4[i];
        s += __expf(v.x - M) + __expf(v.y - M) + __expf(v.z - M) + __expf(v.w - M);
    }
    float S = block_sum<8>(s, red);

    if (tid == 0){
        int tg = tgts[row];
        float v = (tg != EOS_TOK) ? 1.f : 0.f;
        nll[row] = v * ((M + __logf(S)) - x[tg]);
        validf[row] = v;
    }
}

__global__ void loss_reduce_kernel(const float* __restrict__ nll, const float* __restrict__ val,
                                   float* __restrict__ out_loss){
    __shared__ float red[8];
    int t = threadIdx.x;  // 256 threads
    float v = 0.f;
    if (t < TT){
        float s = 0.f, c = 0.f;
        for (int b=0;b<BB;b++){ s += nll[b*TT + t]; c += val[b*TT + t]; }
        v = s / fmaxf(c, 1.f);
    }
    float tot = block_sum<8>(v, red);
    if (t == 0) out_loss[0] = tot;
}

// ---------------- host side ----------------
static void launch_gemm_f32(int transb, int epi,
                            const float* A, const float* Bm, const float* bias, const float* res,
                            float* C, int M, int N, int K,
                            long sA, long sB, long sC, long sR, int batch){
    dim3 gr((N + 63)/64, (M + 63)/64, batch);
    dim3 bl(256);
    if (transb){
        if (epi == 0)      gemm_kernel<1,0><<<gr,bl>>>(A,Bm,bias,res,C,M,N,K,sA,sB,sC,sR);
        else if (epi == 1) gemm_kernel<1,1><<<gr,bl>>>(A,Bm,bias,res,C,M,N,K,sA,sB,sC,sR);
        else               gemm_kernel<1,2><<<gr,bl>>>(A,Bm,bias,res,C,M,N,K,sA,sB,sC,sR);
    } else {
        if (epi == 0)      gemm_kernel<0,0><<<gr,bl>>>(A,Bm,bias,res,C,M,N,K,sA,sB,sC,sR);
        else               gemm_kernel<0,3><<<gr,bl>>>(A,Bm,bias,res,C,M,N,K,sA,sB,sC,sR);
    }
}

static void launch_gemm_tf32(int transb, int epi,
                             const float* A, const float* Bm, const float* bias, const float* res,
                             float* C, int M, int N, int K,
                             long sA, long sB, long sC, long sR, int batch){
    dim3 gr((N + 63)/64, (M + 63)/64, batch);
    dim3 bl(256);
    if (transb){
        if (epi == 0)      gemm_tf32_kernel<1,0><<<gr,bl>>>(A,Bm,bias,res,C,M,N,K,sA,sB,sC,sR);
        else if (epi == 1) gemm_tf32_kernel<1,1><<<gr,bl>>>(A,Bm,bias,res,C,M,N,K,sA,sB,sC,sR);
        else               gemm_tf32_kernel<1,2><<<gr,bl>>>(A,Bm,bias,res,C,M,N,K,sA,sB,sC,sR);
    } else {
        if (epi == 0)      gemm_tf32_kernel<0,0><<<gr,bl>>>(A,Bm,bias,res,C,M,N,K,sA,sB,sC,sR);
        else               gemm_tf32_kernel<0,3><<<gr,bl>>>(A,Bm,bias,res,C,M,N,K,sA,sB,sC,sR);
    }
}

template<typename T> static T* sym(const void* s){
    void* p = nullptr;
    cudaGetSymbolAddress(&p, s);
    return (T*)p;
}

extern "C" void kernel_launch(void* const* d_in, const int* in_sizes, int n_in,
                              void* d_out, int out_size){
    const int*   srcs        = (const int*)  d_in[0];
    const int*   tgts        = (const int*)  d_in[1];
    const int*   law_tokens  = (const int*)  d_in[2];
    const float* src_embed   = (const float*)d_in[3];
    const float* enc_rnn_Wih = (const float*)d_in[4];
    const float* enc_rnn_Whh = (const float*)d_in[5];
    const float* enc_rnn_bih = (const float*)d_in[6];
    const float* enc_rnn_bhh = (const float*)d_in[7];
    const float* enc_gru_Wih = (const float*)d_in[8];
    const float* enc_gru_Whh = (const float*)d_in[9];
    const float* enc_gru_bih = (const float*)d_in[10];
    const float* enc_gru_bhh = (const float*)d_in[11];
    const float* dec_embed   = (const float*)d_in[12];
    const float* dec_rnn_Wih = (const float*)d_in[13];
    const float* dec_rnn_Whh = (const float*)d_in[14];
    const float* dec_rnn_bih = (const float*)d_in[15];
    const float* dec_rnn_bhh = (const float*)d_in[16];
    const float* Ww          = (const float*)d_in[17];
    const float* bw          = (const float*)d_in[18];
    const float* Wp          = (const float*)d_in[19];
    const float* bp          = (const float*)d_in[20];
    const float* Wc          = (const float*)d_in[21];
    const float* bc          = (const float*)d_in[22];
    float* out = (float*)d_out;

    float* h0       = sym<float>(g_h0);
    float* emb_src  = sym<float>(g_emb_src);
    float* gi       = sym<float>(g_gi);
    float* enc1     = sym<float>(g_enc_outs1);
    float* chh      = sym<float>(g_chh);
    int*   leg_toks = sym<int>(g_legal_toks);
    float* emb_leg  = sym<float>(g_emb_leg);
    float* gi_leg   = sym<float>(g_gi_leg);
    float* legals   = sym<float>(g_legals);
    float* att      = sym<float>(g_att);
    float* ca       = sym<float>(g_ca);
    float* enc2     = sym<float>(g_enc_outs);
    int*   dec_in   = sym<int>(g_dec_in);
    float* emb_dec  = sym<float>(g_emb_dec);
    float* gi_dec   = sym<float>(g_gi_dec);
    float* dec_outb = sym<float>(g_dec_out);
    float* scores   = sym<float>(g_scores);
    float* ctx      = sym<float>(g_ctx);
    float* cat      = sym<float>(g_concat);
    float* co       = sym<float>(g_co);
    float* nll      = sym<float>(g_nll);
    float* valf     = sym<float>(g_val);

    // h0 = zeros
    zero_kernel<<<(BB*HH + 255)/256, 256>>>(h0, BB*HH);

    // ---- encoder pass 1 (fp32: feeds charge argmax) ----
    {
        long n = (long)BB*LS*EE;
        gather_kernel<<<(unsigned)((n + 255)/256), 256>>>(emb_src, src_embed, srcs, (long)BB*LS, EE);
    }
    launch_gemm_f32(1, 1, emb_src, enc_rnn_Wih, enc_rnn_bih, nullptr, gi,
                    BB*LS, G3, EE, 0, 0, 0, 0, 1);
    gru_seq_kernel<<<4*BB, 256>>>(gi, LS, enc_rnn_Whh, enc_rnn_bhh, h0, HH, 0, enc1);

    // ---- charge prediction + legal tokens (fp32) ----
    mean_kernel<<<BB, 160>>>(enc1, chh);
    charge_kernel<<<BB, 128>>>(chh, Wc, bc, law_tokens, out + OUT_CHARGE, leg_toks);

    // ---- legal encoding (post-argmax: tf32) ----
    {
        long n = (long)BB*LL*EE;
        gather_kernel<<<(unsigned)((n + 255)/256), 256>>>(emb_leg, src_embed, leg_toks, (long)BB*LL, EE);
    }
    launch_gemm_tf32(1, 1, emb_leg, enc_rnn_Wih, enc_rnn_bih, nullptr, gi_leg,
                     BB*LL, G3, EE, 0, 0, 0, 0, 1);
    gru_seq_kernel<<<4*BB, 256>>>(gi_leg, LL, enc_rnn_Whh, enc_rnn_bhh, h0, HH, 0, legals);

    // ---- mask attention (tf32) ----
    launch_gemm_tf32(1, 0, enc1, legals, nullptr, nullptr, att,
                     LS, LL, HH, (long)LS*HH, (long)LL*HH, (long)LS*LL, 0, BB);
    mask_softmax128<<<BB*LS, 128>>>(att);
    launch_gemm_tf32(0, 3, att, legals, nullptr, enc1, ca,
                     LS, HH, LL, (long)LS*LL, (long)LL*HH, (long)LS*HH, (long)LS*HH, BB);

    // ---- encoder pass 2 (tf32 gi) ----
    launch_gemm_tf32(1, 1, ca, enc_gru_Wih, enc_gru_bih, nullptr, gi,
                     BB*LS, G3, HH, 0, 0, 0, 0, 1);
    gru_seq_kernel<<<4*BB, 256>>>(gi, LS, enc_gru_Whh, enc_gru_bhh, h0, HH, 0, enc2);

    // ---- decoder GRU (teacher forcing, tf32 gi), h0 = enc2[:,511,:] ----
    dec_tokens_kernel<<<(BB*TT + 255)/256, 256>>>(tgts, dec_in);
    {
        long n = (long)BB*TT*EE;
        gather_kernel<<<(unsigned)((n + 255)/256), 256>>>(emb_dec, dec_embed, dec_in, (long)BB*TT, EE);
    }
    launch_gemm_tf32(1, 1, emb_dec, dec_rnn_Wih, dec_rnn_bih, nullptr, gi_dec,
                     BB*TT, G3, EE, 0, 0, 0, 0, 1);
    gru_seq_kernel<<<4*BB, 256>>>(gi_dec, TT, dec_rnn_Whh, dec_rnn_bhh,
                                  enc2, (long)LS*HH, (long)(LS-1)*HH, dec_outb);

    // ---- decoder attention (tf32) ----
    launch_gemm_tf32(1, 0, dec_outb, enc2, nullptr, nullptr, scores,
                     TT, LS, HH, (long)TT*HH, (long)LS*HH, (long)TT*LS, 0, BB);
    softmax512<<<BB*TT, 256>>>(scores);
    launch_gemm_tf32(0, 0, scores, enc2, nullptr, nullptr, ctx,
                     TT, HH, LS, (long)TT*LS, (long)LS*HH, (long)TT*HH, 0, BB);

    // ---- co = tanh([dec_out|ctx] @ Ww^T + bw) (tf32) ----
    {
        long n = (long)BB*TT*2*HH;
        concat_kernel<<<(unsigned)((n + 255)/256), 256>>>(dec_outb, ctx, cat);
    }
    launch_gemm_tf32(1, 2, cat, Ww, bw, nullptr, co,
                     BB*TT, HH, 2*HH, 0, 0, 0, 0, 1);

    // ---- logits = co @ Wp^T + bp (tf32 tensor cores), stored transposed into d_out ----
    {
        dim3 gr((VV + 127)/128, (BB*TT)/128, 1);
        logits_tf32_kernel<<<gr, 256>>>(co, Wp, bp, out, BB*TT, VV, HH);
    }

    // ---- loss ----
    nll_kernel<<<BB*TT, 256>>>(out, tgts, nll, valf);
    loss_reduce_kernel<<<1, 256>>>(nll, valf, out + OUT_LOSS);
}